// round 11
// baseline (speedup 1.0000x reference)
#include <cuda_runtime.h>
#include <cuda_fp16.h>
#include <cstdint>

#define NTOK 32768
#define DIM 1024
#define NEXP 8
#define NROWS (NTOK * 2)

// ---------------- device scratch (no allocation allowed) ----------------
__device__ int   g_cnt[NEXP];
__device__ int   g_off[NEXP + 1];
__device__ int   g_cur2[NEXP];
__device__ int   g_tok[NROWS];
__device__ float g_wt[NROWS];
__device__ int   g_topi[NTOK];
__device__ float g_w0[NTOK];
__device__ float g_w1[NTOK];
__device__ int   g_slot0[NTOK];
__device__ int   g_slot1[NTOK];
__device__ __half g_xf[(size_t)NTOK * DIM];            // fp16 x
__device__ __half g_wf[(size_t)NEXP * DIM * DIM];      // fp16 W
__device__ __half g_scr[(size_t)NROWS * DIM];          // fp16 slot scratch (128 MB)

// ---------------- PTX helpers (base-target PTX only) ----------------
__device__ __forceinline__ uint32_t smem_u32(const void* p) {
    uint32_t a;
    asm("{ .reg .u64 t; cvta.to.shared.u64 t, %1; cvt.u32.u64 %0, t; }" : "=r"(a) : "l"(p));
    return a;
}
__device__ __forceinline__ void cp16(uint32_t dst, const void* src) {
    asm volatile("cp.async.cg.shared.global [%0], [%1], 16;" :: "r"(dst), "l"(src));
}
#define CP_COMMIT() asm volatile("cp.async.commit_group;" ::: "memory")

#define LDSM4(r, addr) \
    asm volatile("ldmatrix.sync.aligned.m8n8.x4.shared.b16 {%0,%1,%2,%3}, [%4];" \
        : "=r"((r)[0]), "=r"((r)[1]), "=r"((r)[2]), "=r"((r)[3]) : "r"(addr))

#define MMA16816(d, a, b0, b1) \
    asm volatile("mma.sync.aligned.m16n8k16.row.col.f32.f16.f16.f32 " \
        "{%0,%1,%2,%3},{%4,%5,%6,%7},{%8,%9},{%0,%1,%2,%3};" \
        : "+f"((d)[0]), "+f"((d)[1]), "+f"((d)[2]), "+f"((d)[3]) \
        : "r"((a)[0]), "r"((a)[1]), "r"((a)[2]), "r"((a)[3]), "r"(b0), "r"(b1))

// ---------------- 1) convert W fp32 -> fp16 (+ zero counters, folded) -----
__global__ void conv_w_kernel(const float* __restrict__ W) {
    if (blockIdx.x == 0 && threadIdx.x < NEXP) {
        g_cnt[threadIdx.x] = 0;
        g_cur2[threadIdx.x] = 0;
    }
    int i = blockIdx.x * 256 + threadIdx.x;
    float4 v = reinterpret_cast<const float4*>(W)[i];
    __half2 a = {__float2half(v.x), __float2half(v.y)};
    __half2 b = {__float2half(v.z), __float2half(v.w)};
    reinterpret_cast<__half2*>(g_wf)[i * 2 + 0] = a;
    reinterpret_cast<__half2*>(g_wf)[i * 2 + 1] = b;
}

// ---------------- 2) gating (vectorized) + fused x->fp16 conversion -------
__global__ void gating_kernel(const float* __restrict__ x,
                              const float* __restrict__ Wg,
                              const float* __restrict__ bg) {
    __shared__ float4 sWg4[NEXP * 256];     // 32 KB
    __shared__ float sbg[NEXP];
    int tid = threadIdx.x;
    for (int i = tid; i < NEXP * 256; i += 256)
        sWg4[i] = reinterpret_cast<const float4*>(Wg)[i];
    if (tid < NEXP) sbg[tid] = bg[tid];
    __syncthreads();

    int warp = tid >> 5, lane = tid & 31;
    int t = blockIdx.x * 8 + warp;
    const float4* xr4 = reinterpret_cast<const float4*>(x) + (size_t)t * 256;
    __half2* xo2 = reinterpret_cast<__half2*>(g_xf) + (size_t)t * 512;

    float acc[NEXP];
#pragma unroll
    for (int e = 0; e < NEXP; e++) acc[e] = 0.f;

#pragma unroll
    for (int it = 0; it < 8; it++) {
        int j4 = it * 32 + lane;
        float4 xv = xr4[j4];
        __half2 h0 = {__float2half(xv.x), __float2half(xv.y)};
        __half2 h1 = {__float2half(xv.z), __float2half(xv.w)};
        xo2[j4 * 2 + 0] = h0;
        xo2[j4 * 2 + 1] = h1;
#pragma unroll
        for (int e = 0; e < NEXP; e++) {
            float4 wv = sWg4[e * 256 + j4];
            acc[e] += xv.x * wv.x + xv.y * wv.y + xv.z * wv.z + xv.w * wv.w;
        }
    }
#pragma unroll
    for (int e = 0; e < NEXP; e++)
#pragma unroll
        for (int o = 16; o; o >>= 1) acc[e] += __shfl_xor_sync(0xffffffffu, acc[e], o);

    if (lane == 0) {
        float s[NEXP], m = -1e30f;
#pragma unroll
        for (int e = 0; e < NEXP; e++) { s[e] = acc[e] + sbg[e]; m = fmaxf(m, s[e]); }
        float p[NEXP], sum = 0.f;
#pragma unroll
        for (int e = 0; e < NEXP; e++) { p[e] = __expf(s[e] - m); sum += p[e]; }
        float inv = 1.f / sum;
#pragma unroll
        for (int e = 0; e < NEXP; e++) p[e] *= inv;
        int i0 = 0;
#pragma unroll
        for (int e = 1; e < NEXP; e++) if (p[e] > p[i0]) i0 = e;
        int i1 = -1;
#pragma unroll
        for (int e = 0; e < NEXP; e++) {
            if (e == i0) continue;
            if (i1 < 0 || p[e] > p[i1]) i1 = e;
        }
        g_topi[t] = i0 | (i1 << 8);
        g_w0[t] = p[i0];
        g_w1[t] = p[i1];
        atomicAdd(&g_cnt[i0], 1);
        atomicAdd(&g_cnt[i1], 1);
    }
}

// ---------------- 3) scatter (local prefix scan; no separate scan kernel) -
__global__ void scatter_kernel() {
    __shared__ int soff[NEXP];
    if (threadIdx.x == 0) {
        int o = 0;
#pragma unroll
        for (int e = 0; e < NEXP; e++) { soff[e] = o; o += g_cnt[e]; }
        if (blockIdx.x == 0) {          // publish for the GEMM kernel
            int o2 = 0;
#pragma unroll
            for (int e = 0; e < NEXP; e++) { g_off[e] = o2; o2 += g_cnt[e]; }
            g_off[NEXP] = o2;
        }
    }
    __syncthreads();
    int t = blockIdx.x * blockDim.x + threadIdx.x;
    int pk = g_topi[t];
    int i0 = pk & 0xff, i1 = (pk >> 8) & 0xff;
    int p0 = soff[i0] + atomicAdd(&g_cur2[i0], 1);
    g_tok[p0] = t; g_wt[p0] = g_w0[t]; g_slot0[t] = p0;
    int p1 = soff[i1] + atomicAdd(&g_cur2[i1], 1);
    g_tok[p1] = t; g_wt[p1] = g_w1[t]; g_slot1[t] = p1;
}

// ---------------- 4) grouped GEMM (128x128, 32x64 warps, 1-sync mainloop) -
#define KCHUNK 32
#define NSTG 4
#define ROWB 80
#define STG_A 0
#define STG_B 10240
#define STG_SZ 20480
#define HDR 2048
#define SMEM_TOTAL (HDR + NSTG * STG_SZ)   // 83968

extern __shared__ __align__(1024) char dyn_smem[];

struct GArgs {
    uint32_t sbase;
    const int* stok;
    int wbase;     // e*DIM + col0
    int tid;
};

__device__ __forceinline__ void load_stage(const GArgs& a, int stage, int k0) {
    uint32_t st = a.sbase + HDR + stage * STG_SZ;
#pragma unroll
    for (int q = 0; q < 2; q++) {               // A: 128 rows x 4 16B-chunks
        int idx = q * 256 + a.tid;
        int row = idx >> 2, c = idx & 3;
        size_t src = (size_t)a.stok[row] * DIM + k0 + c * 8;
        cp16(st + STG_A + row * ROWB + c * 16, g_xf + src);
    }
#pragma unroll
    for (int q = 0; q < 2; q++) {               // B
        int idx = q * 256 + a.tid;
        int row = idx >> 2, c = idx & 3;
        size_t src = (size_t)(a.wbase + row) * DIM + k0 + c * 8;
        cp16(st + STG_B + row * ROWB + c * 16, g_wf + src);
    }
    CP_COMMIT();
}

__device__ __forceinline__ void compute_stage(uint32_t st, int m0, int n0, int lane,
                                              float acc[2][8][4]) {
#pragma unroll
    for (int ks = 0; ks < 2; ks++) {
        uint32_t a[2][4];
#pragma unroll
        for (int fi = 0; fi < 2; fi++) {
            uint32_t addr = st + STG_A + (uint32_t)(m0 + fi * 16 + (lane & 15)) * ROWB
                          + ks * 32 + ((lane >> 4) << 4);
            LDSM4(a[fi], addr);
        }
#pragma unroll
        for (int fj2 = 0; fj2 < 4; fj2++) {
            uint32_t b[4];
            uint32_t addr = st + STG_B
                + (uint32_t)(n0 + fj2 * 16 + (((lane >> 4) & 1) << 3) + (lane & 7)) * ROWB
                + ks * 32 + (((lane >> 3) & 1) << 4);
            LDSM4(b, addr);
            MMA16816(acc[0][2 * fj2 + 0], a[0], b[0], b[1]);
            MMA16816(acc[0][2 * fj2 + 1], a[0], b[2], b[3]);
            MMA16816(acc[1][2 * fj2 + 0], a[1], b[0], b[1]);
            MMA16816(acc[1][2 * fj2 + 1], a[1], b[2], b[3]);
        }
    }
}

__global__ __launch_bounds__(256, 2)
void moe_gemm_mma(const float* __restrict__ bias) {
    int e = blockIdx.z;
    int base = g_off[e];
    int cnt = g_off[e + 1] - base;
    int row0 = blockIdx.y * 128;
    if (row0 >= cnt) return;
    int col0 = blockIdx.x * 128;

    int* stok = reinterpret_cast<int*>(dyn_smem);
    float* swt = reinterpret_cast<float*>(dyn_smem + 512);
    float* sbias = reinterpret_cast<float*>(dyn_smem + 1024);

    int tid = threadIdx.x;
    if (tid < 128) {
        int p = row0 + tid;
        int pc = p < cnt ? p : cnt - 1;
        stok[tid] = g_tok[base + pc];
        swt[tid] = (p < cnt) ? g_wt[base + p] : 0.f;
    }
    if (tid < 32)
        reinterpret_cast<float4*>(sbias)[tid] =
            reinterpret_cast<const float4*>(bias + e * DIM + col0)[tid];
    __syncthreads();

    uint32_t sbase = smem_u32(dyn_smem);
    GArgs ga{sbase, stok, e * DIM + col0, tid};

    load_stage(ga, 0, 0);
    load_stage(ga, 1, KCHUNK);
    load_stage(ga, 2, 2 * KCHUNK);

    int lane = tid & 31, wid = tid >> 5;
    int m0 = (wid & 3) * 32, n0 = (wid >> 2) * 64;

    float acc[2][8][4];
#pragma unroll
    for (int i = 0; i < 2; i++)
#pragma unroll
        for (int j = 0; j < 8; j++)
#pragma unroll
            for (int k = 0; k < 4; k++) acc[i][j][k] = 0.f;

    const int NIT = DIM / KCHUNK;   // 32
    for (int i = 0; i < NIT; i++) {
        int s = i & 3;
        asm volatile("cp.async.wait_group 2;" ::: "memory");
        __syncthreads();
        // Loads target stage (i+3)&3 == (i-1)&3, which every warp finished
        // reading in iter i-1 (proven by the sync above). Tail iterations
        // commit an empty group to keep "group i complete at iter i" exact.
        if (i + 3 < NIT) load_stage(ga, (i + 3) & 3, (i + 3) * KCHUNK);
        else CP_COMMIT();
        compute_stage(sbase + HDR + s * STG_SZ, m0, n0, lane, acc);
    }

    // epilogue: scaled (+bias) fp16 write to slot scratch
    int tq = lane >> 2, tr = lane & 3;
#pragma unroll
    for (int fi = 0; fi < 2; fi++) {
#pragma unroll
        for (int h = 0; h < 2; h++) {
            int m = m0 + fi * 16 + h * 8 + tq;
            int gr = row0 + m;
            if (gr < cnt) {
                float w = swt[m];
                __half* orow = g_scr + (size_t)(base + gr) * DIM + col0;
#pragma unroll
                for (int fj = 0; fj < 8; fj++) {
                    int cn = n0 + fj * 8 + tr * 2;
                    float vx = w * (acc[fi][fj][h * 2 + 0] + sbias[cn]);
                    float vy = w * (acc[fi][fj][h * 2 + 1] + sbias[cn + 1]);
                    *reinterpret_cast<__half2*>(orow + cn) = __floats2half2_rn(vx, vy);
                }
            }
        }
    }
}

// ---------------- 5) combine (fp16 scr -> fp32 out) ----------------
__global__ void combine_kernel(float* __restrict__ out) {
    int idx = blockIdx.x * 256 + threadIdx.x;   // 8-half chunk index
    int t = idx >> 7;                            // 128 chunks per token
    int c = idx & 127;
    const uint4* s4 = reinterpret_cast<const uint4*>(g_scr);
    uint4 a = s4[(size_t)g_slot0[t] * 128 + c];
    uint4 b = s4[(size_t)g_slot1[t] * 128 + c];
    const __half2* ah = reinterpret_cast<const __half2*>(&a);
    const __half2* bh = reinterpret_cast<const __half2*>(&b);
    float4 o0, o1;
    float2 p0 = __half22float2(ah[0]), q0 = __half22float2(bh[0]);
    float2 p1 = __half22float2(ah[1]), q1 = __half22float2(bh[1]);
    float2 p2 = __half22float2(ah[2]), q2 = __half22float2(bh[2]);
    float2 p3 = __half22float2(ah[3]), q3 = __half22float2(bh[3]);
    o0.x = p0.x + q0.x; o0.y = p0.y + q0.y; o0.z = p1.x + q1.x; o0.w = p1.y + q1.y;
    o1.x = p2.x + q2.x; o1.y = p2.y + q2.y; o1.z = p3.x + q3.x; o1.w = p3.y + q3.y;
    float4* out4 = reinterpret_cast<float4*>(out);
    out4[idx * 2 + 0] = o0;
    out4[idx * 2 + 1] = o1;
}

// ---------------------------------------------------------------------------
extern "C" void kernel_launch(void* const* d_in, const int* in_sizes, int n_in,
                              void* d_out, int out_size) {
    const float* x  = (const float*)d_in[0];
    const float* Wg = (const float*)d_in[1];
    const float* bg = (const float*)d_in[2];
    const float* W  = (const float*)d_in[3];
    const float* b  = (const float*)d_in[4];
    float* out = (float*)d_out;

    cudaFuncSetAttribute(moe_gemm_mma, cudaFuncAttributeMaxDynamicSharedMemorySize,
                         SMEM_TOTAL);

    conv_w_kernel<<<(NEXP * DIM * DIM) / (4 * 256), 256>>>(W);
    gating_kernel<<<NTOK / 8, 256>>>(x, Wg, bg);
    scatter_kernel<<<NTOK / 256, 256>>>();
    moe_gemm_mma<<<dim3(8, 512, 8), 256, SMEM_TOTAL>>>(b);
    combine_kernel<<<(NTOK * DIM) / (8 * 256), 256>>>(out);
}

// round 12
// speedup vs baseline: 1.0391x; 1.0391x over previous
#include <cuda_runtime.h>
#include <cuda_fp16.h>
#include <cstdint>

#define NTOK 32768
#define DIM 1024
#define NEXP 8
#define NROWS (NTOK * 2)

// ---------------- device scratch (no allocation allowed) ----------------
__device__ int   g_cnt[NEXP];
__device__ int   g_off[NEXP + 1];
__device__ int   g_cur2[NEXP];
__device__ int   g_tok[NROWS];
__device__ float g_wt[NROWS];
__device__ int   g_topi[NTOK];
__device__ float g_w0[NTOK];
__device__ float g_w1[NTOK];
__device__ int   g_slot0[NTOK];
__device__ int   g_slot1[NTOK];
__device__ __half g_xf[(size_t)NTOK * DIM];            // fp16 x
__device__ __half g_wf[(size_t)NEXP * DIM * DIM];      // fp16 W
__device__ __half g_scr[(size_t)NROWS * DIM];          // fp16 slot scratch (128 MB)

// ---------------- PTX helpers (base-target PTX only) ----------------
__device__ __forceinline__ uint32_t smem_u32(const void* p) {
    uint32_t a;
    asm("{ .reg .u64 t; cvta.to.shared.u64 t, %1; cvt.u32.u64 %0, t; }" : "=r"(a) : "l"(p));
    return a;
}
__device__ __forceinline__ void cp16(uint32_t dst, const void* src) {
    asm volatile("cp.async.cg.shared.global [%0], [%1], 16;" :: "r"(dst), "l"(src));
}
#define CP_COMMIT() asm volatile("cp.async.commit_group;" ::: "memory")

#define LDSM4(r, addr) \
    asm volatile("ldmatrix.sync.aligned.m8n8.x4.shared.b16 {%0,%1,%2,%3}, [%4];" \
        : "=r"((r)[0]), "=r"((r)[1]), "=r"((r)[2]), "=r"((r)[3]) : "r"(addr))

#define MMA16816(d, a, b0, b1) \
    asm volatile("mma.sync.aligned.m16n8k16.row.col.f32.f16.f16.f32 " \
        "{%0,%1,%2,%3},{%4,%5,%6,%7},{%8,%9},{%0,%1,%2,%3};" \
        : "+f"((d)[0]), "+f"((d)[1]), "+f"((d)[2]), "+f"((d)[3]) \
        : "r"((a)[0]), "r"((a)[1]), "r"((a)[2]), "r"((a)[3]), "r"(b0), "r"(b1))

// ---------------- 1) convert W fp32 -> fp16 (+ zero counters, folded) -----
__global__ void conv_w_kernel(const float* __restrict__ W) {
    if (blockIdx.x == 0 && threadIdx.x < NEXP) {
        g_cnt[threadIdx.x] = 0;
        g_cur2[threadIdx.x] = 0;
    }
    int i = blockIdx.x * 256 + threadIdx.x;
    float4 v = reinterpret_cast<const float4*>(W)[i];
    __half2 a = {__float2half(v.x), __float2half(v.y)};
    __half2 b = {__float2half(v.z), __float2half(v.w)};
    reinterpret_cast<__half2*>(g_wf)[i * 2 + 0] = a;
    reinterpret_cast<__half2*>(g_wf)[i * 2 + 1] = b;
}

// ---------------- 2) gating (vectorized) + fused x->fp16 conversion -------
__global__ void gating_kernel(const float* __restrict__ x,
                              const float* __restrict__ Wg,
                              const float* __restrict__ bg) {
    __shared__ float4 sWg4[NEXP * 256];     // 32 KB
    __shared__ float sbg[NEXP];
    int tid = threadIdx.x;
    for (int i = tid; i < NEXP * 256; i += 256)
        sWg4[i] = reinterpret_cast<const float4*>(Wg)[i];
    if (tid < NEXP) sbg[tid] = bg[tid];
    __syncthreads();

    int warp = tid >> 5, lane = tid & 31;
    int t = blockIdx.x * 8 + warp;
    const float4* xr4 = reinterpret_cast<const float4*>(x) + (size_t)t * 256;
    __half2* xo2 = reinterpret_cast<__half2*>(g_xf) + (size_t)t * 512;

    float acc[NEXP];
#pragma unroll
    for (int e = 0; e < NEXP; e++) acc[e] = 0.f;

#pragma unroll
    for (int it = 0; it < 8; it++) {
        int j4 = it * 32 + lane;
        float4 xv = xr4[j4];
        __half2 h0 = {__float2half(xv.x), __float2half(xv.y)};
        __half2 h1 = {__float2half(xv.z), __float2half(xv.w)};
        xo2[j4 * 2 + 0] = h0;
        xo2[j4 * 2 + 1] = h1;
#pragma unroll
        for (int e = 0; e < NEXP; e++) {
            float4 wv = sWg4[e * 256 + j4];
            acc[e] += xv.x * wv.x + xv.y * wv.y + xv.z * wv.z + xv.w * wv.w;
        }
    }
#pragma unroll
    for (int e = 0; e < NEXP; e++)
#pragma unroll
        for (int o = 16; o; o >>= 1) acc[e] += __shfl_xor_sync(0xffffffffu, acc[e], o);

    if (lane == 0) {
        float s[NEXP], m = -1e30f;
#pragma unroll
        for (int e = 0; e < NEXP; e++) { s[e] = acc[e] + sbg[e]; m = fmaxf(m, s[e]); }
        float p[NEXP], sum = 0.f;
#pragma unroll
        for (int e = 0; e < NEXP; e++) { p[e] = __expf(s[e] - m); sum += p[e]; }
        float inv = 1.f / sum;
#pragma unroll
        for (int e = 0; e < NEXP; e++) p[e] *= inv;
        int i0 = 0;
#pragma unroll
        for (int e = 1; e < NEXP; e++) if (p[e] > p[i0]) i0 = e;
        int i1 = -1;
#pragma unroll
        for (int e = 0; e < NEXP; e++) {
            if (e == i0) continue;
            if (i1 < 0 || p[e] > p[i1]) i1 = e;
        }
        g_topi[t] = i0 | (i1 << 8);
        g_w0[t] = p[i0];
        g_w1[t] = p[i1];
        atomicAdd(&g_cnt[i0], 1);
        atomicAdd(&g_cnt[i1], 1);
    }
}

// ---------------- 3) scatter (local prefix scan; no separate scan kernel) -
__global__ void scatter_kernel() {
    __shared__ int soff[NEXP];
    if (threadIdx.x == 0) {
        int o = 0;
#pragma unroll
        for (int e = 0; e < NEXP; e++) { soff[e] = o; o += g_cnt[e]; }
        if (blockIdx.x == 0) {          // publish for the GEMM kernel
            int o2 = 0;
#pragma unroll
            for (int e = 0; e < NEXP; e++) { g_off[e] = o2; o2 += g_cnt[e]; }
            g_off[NEXP] = o2;
        }
    }
    __syncthreads();
    int t = blockIdx.x * blockDim.x + threadIdx.x;
    int pk = g_topi[t];
    int i0 = pk & 0xff, i1 = (pk >> 8) & 0xff;
    int p0 = soff[i0] + atomicAdd(&g_cur2[i0], 1);
    g_tok[p0] = t; g_wt[p0] = g_w0[t]; g_slot0[t] = p0;
    int p1 = soff[i1] + atomicAdd(&g_cur2[i1], 1);
    g_tok[p1] = t; g_wt[p1] = g_w1[t]; g_slot1[t] = p1;
}

// ---------------- 4) grouped GEMM: loads interleaved between ksteps -------
#define KCHUNK 32
#define NSTG 4
#define ROWB 80
#define STG_A 0
#define STG_B 10240
#define STG_SZ 20480
#define HDR 2048
#define SMEM_TOTAL (HDR + NSTG * STG_SZ)   // 83968

extern __shared__ __align__(1024) char dyn_smem[];

struct GArgs {
    uint32_t sbase;
    const int* stok;
    int wbase;     // e*DIM + col0
    int tid;
};

__device__ __forceinline__ void load_stage(const GArgs& a, int stage, int k0) {
    uint32_t st = a.sbase + HDR + stage * STG_SZ;
#pragma unroll
    for (int q = 0; q < 2; q++) {               // A: 128 rows x 4 16B-chunks
        int idx = q * 256 + a.tid;
        int row = idx >> 2, c = idx & 3;
        size_t src = (size_t)a.stok[row] * DIM + k0 + c * 8;
        cp16(st + STG_A + row * ROWB + c * 16, g_xf + src);
    }
#pragma unroll
    for (int q = 0; q < 2; q++) {               // B
        int idx = q * 256 + a.tid;
        int row = idx >> 2, c = idx & 3;
        size_t src = (size_t)(a.wbase + row) * DIM + k0 + c * 8;
        cp16(st + STG_B + row * ROWB + c * 16, g_wf + src);
    }
    CP_COMMIT();
}

// One K=16 step: 6 LDSM + 16 MMA (fragment registers live only inside).
__device__ __forceinline__ void compute_kstep(uint32_t st, int m0, int n0, int lane,
                                              int ks, float acc[2][8][4]) {
    uint32_t a[2][4];
#pragma unroll
    for (int fi = 0; fi < 2; fi++) {
        uint32_t addr = st + STG_A + (uint32_t)(m0 + fi * 16 + (lane & 15)) * ROWB
                      + ks * 32 + ((lane >> 4) << 4);
        LDSM4(a[fi], addr);
    }
#pragma unroll
    for (int fj2 = 0; fj2 < 4; fj2++) {
        uint32_t b[4];
        uint32_t addr = st + STG_B
            + (uint32_t)(n0 + fj2 * 16 + (((lane >> 4) & 1) << 3) + (lane & 7)) * ROWB
            + ks * 32 + (((lane >> 3) & 1) << 4);
        LDSM4(b, addr);
        MMA16816(acc[0][2 * fj2 + 0], a[0], b[0], b[1]);
        MMA16816(acc[0][2 * fj2 + 1], a[0], b[2], b[3]);
        MMA16816(acc[1][2 * fj2 + 0], a[1], b[0], b[1]);
        MMA16816(acc[1][2 * fj2 + 1], a[1], b[2], b[3]);
    }
}

__global__ __launch_bounds__(256, 2)
void moe_gemm_mma(const float* __restrict__ bias) {
    int e = blockIdx.z;
    int base = g_off[e];
    int cnt = g_off[e + 1] - base;
    int row0 = blockIdx.y * 128;
    if (row0 >= cnt) return;
    int col0 = blockIdx.x * 128;

    int* stok = reinterpret_cast<int*>(dyn_smem);
    float* swt = reinterpret_cast<float*>(dyn_smem + 512);
    float* sbias = reinterpret_cast<float*>(dyn_smem + 1024);

    int tid = threadIdx.x;
    if (tid < 128) {
        int p = row0 + tid;
        int pc = p < cnt ? p : cnt - 1;
        stok[tid] = g_tok[base + pc];
        swt[tid] = (p < cnt) ? g_wt[base + p] : 0.f;
    }
    if (tid < 32)
        reinterpret_cast<float4*>(sbias)[tid] =
            reinterpret_cast<const float4*>(bias + e * DIM + col0)[tid];
    __syncthreads();

    uint32_t sbase = smem_u32(dyn_smem);
    GArgs ga{sbase, stok, e * DIM + col0, tid};

    load_stage(ga, 0, 0);
    load_stage(ga, 1, KCHUNK);
    load_stage(ga, 2, 2 * KCHUNK);

    int lane = tid & 31, wid = tid >> 5;
    int m0 = (wid & 3) * 32, n0 = (wid >> 2) * 64;

    float acc[2][8][4];
#pragma unroll
    for (int i = 0; i < 2; i++)
#pragma unroll
        for (int j = 0; j < 8; j++)
#pragma unroll
            for (int k = 0; k < 4; k++) acc[i][j][k] = 0.f;

    const int NIT = DIM / KCHUNK;   // 32
    for (int i = 0; i < NIT; i++) {
        int s = i & 3;
        asm volatile("cp.async.wait_group 2;" ::: "memory");
        __syncthreads();
        uint32_t stg = sbase + HDR + s * STG_SZ;
        // kstep0 MMAs first, THEN the cp.async burst: the warp issues LSU
        // work while its 16 kstep0 MMAs drain through the tensor pipe.
        compute_kstep(stg, m0, n0, lane, 0, acc);
        if (i + 3 < NIT) load_stage(ga, (i + 3) & 3, (i + 3) * KCHUNK);
        else CP_COMMIT();   // tail: keep "group i complete at iter i" exact
        compute_kstep(stg, m0, n0, lane, 1, acc);
    }

    // epilogue: scaled (+bias) fp16 write to slot scratch
    int tq = lane >> 2, tr = lane & 3;
#pragma unroll
    for (int fi = 0; fi < 2; fi++) {
#pragma unroll
        for (int h = 0; h < 2; h++) {
            int m = m0 + fi * 16 + h * 8 + tq;
            int gr = row0 + m;
            if (gr < cnt) {
                float w = swt[m];
                __half* orow = g_scr + (size_t)(base + gr) * DIM + col0;
#pragma unroll
                for (int fj = 0; fj < 8; fj++) {
                    int cn = n0 + fj * 8 + tr * 2;
                    float vx = w * (acc[fi][fj][h * 2 + 0] + sbias[cn]);
                    float vy = w * (acc[fi][fj][h * 2 + 1] + sbias[cn + 1]);
                    *reinterpret_cast<__half2*>(orow + cn) = __floats2half2_rn(vx, vy);
                }
            }
        }
    }
}

// ---------------- 5) combine (fp16 scr -> fp32 out) ----------------
__global__ void combine_kernel(float* __restrict__ out) {
    int idx = blockIdx.x * 256 + threadIdx.x;   // 8-half chunk index
    int t = idx >> 7;                            // 128 chunks per token
    int c = idx & 127;
    const uint4* s4 = reinterpret_cast<const uint4*>(g_scr);
    uint4 a = s4[(size_t)g_slot0[t] * 128 + c];
    uint4 b = s4[(size_t)g_slot1[t] * 128 + c];
    const __half2* ah = reinterpret_cast<const __half2*>(&a);
    const __half2* bh = reinterpret_cast<const __half2*>(&b);
    float4 o0, o1;
    float2 p0 = __half22float2(ah[0]), q0 = __half22float2(bh[0]);
    float2 p1 = __half22float2(ah[1]), q1 = __half22float2(bh[1]);
    float2 p2 = __half22float2(ah[2]), q2 = __half22float2(bh[2]);
    float2 p3 = __half22float2(ah[3]), q3 = __half22float2(bh[3]);
    o0.x = p0.x + q0.x; o0.y = p0.y + q0.y; o0.z = p1.x + q1.x; o0.w = p1.y + q1.y;
    o1.x = p2.x + q2.x; o1.y = p2.y + q2.y; o1.z = p3.x + q3.x; o1.w = p3.y + q3.y;
    float4* out4 = reinterpret_cast<float4*>(out);
    out4[idx * 2 + 0] = o0;
    out4[idx * 2 + 1] = o1;
}

// ---------------------------------------------------------------------------
extern "C" void kernel_launch(void* const* d_in, const int* in_sizes, int n_in,
                              void* d_out, int out_size) {
    const float* x  = (const float*)d_in[0];
    const float* Wg = (const float*)d_in[1];
    const float* bg = (const float*)d_in[2];
    const float* W  = (const float*)d_in[3];
    const float* b  = (const float*)d_in[4];
    float* out = (float*)d_out;

    cudaFuncSetAttribute(moe_gemm_mma, cudaFuncAttributeMaxDynamicSharedMemorySize,
                         SMEM_TOTAL);

    conv_w_kernel<<<(NEXP * DIM * DIM) / (4 * 256), 256>>>(W);
    gating_kernel<<<NTOK / 8, 256>>>(x, Wg, bg);
    scatter_kernel<<<NTOK / 256, 256>>>();
    moe_gemm_mma<<<dim3(8, 512, 8), 256, SMEM_TOTAL>>>(b);
    combine_kernel<<<(NTOK * DIM) / (8 * 256), 256>>>(out);
}

// round 13
// speedup vs baseline: 1.0851x; 1.0442x over previous
#include <cuda_runtime.h>
#include <cuda_fp16.h>
#include <cstdint>

#define NTOK 32768
#define DIM 1024
#define NEXP 8
#define NROWS (NTOK * 2)

// ---------------- device scratch (no allocation allowed) ----------------
__device__ int   g_cnt[NEXP];
__device__ int   g_off[NEXP + 1];
__device__ int   g_cur2[NEXP];
__device__ int   g_tok[NROWS];
__device__ float g_wt[NROWS];
__device__ int   g_topi[NTOK];
__device__ float g_w0[NTOK];
__device__ float g_w1[NTOK];
__device__ int   g_slot0[NTOK];
__device__ int   g_slot1[NTOK];
__device__ __half g_xf[(size_t)NTOK * DIM];            // fp16 x
__device__ __half g_wf[(size_t)NEXP * DIM * DIM];      // fp16 W
__device__ __half g_scr[(size_t)NROWS * DIM];          // fp16 slot scratch (128 MB)

// ---------------- PTX helpers (base-target PTX only) ----------------
__device__ __forceinline__ uint32_t smem_u32(const void* p) {
    uint32_t a;
    asm("{ .reg .u64 t; cvta.to.shared.u64 t, %1; cvt.u32.u64 %0, t; }" : "=r"(a) : "l"(p));
    return a;
}
__device__ __forceinline__ void cp16(uint32_t dst, const void* src) {
    asm volatile("cp.async.cg.shared.global [%0], [%1], 16;" :: "r"(dst), "l"(src));
}
#define CP_COMMIT() asm volatile("cp.async.commit_group;" ::: "memory")

#define LDSM4(r, addr) \
    asm volatile("ldmatrix.sync.aligned.m8n8.x4.shared.b16 {%0,%1,%2,%3}, [%4];" \
        : "=r"((r)[0]), "=r"((r)[1]), "=r"((r)[2]), "=r"((r)[3]) : "r"(addr))

#define MMA16816(d, a, b0, b1) \
    asm volatile("mma.sync.aligned.m16n8k16.row.col.f32.f16.f16.f32 " \
        "{%0,%1,%2,%3},{%4,%5,%6,%7},{%8,%9},{%0,%1,%2,%3};" \
        : "+f"((d)[0]), "+f"((d)[1]), "+f"((d)[2]), "+f"((d)[3]) \
        : "r"((a)[0]), "r"((a)[1]), "r"((a)[2]), "r"((a)[3]), "r"(b0), "r"(b1))

// ---------------- 1) convert W fp32 -> fp16 (+ zero counters, folded) -----
__global__ void conv_w_kernel(const float* __restrict__ W) {
    if (blockIdx.x == 0 && threadIdx.x < NEXP) {
        g_cnt[threadIdx.x] = 0;
        g_cur2[threadIdx.x] = 0;
    }
    int i = blockIdx.x * 256 + threadIdx.x;
    float4 v = reinterpret_cast<const float4*>(W)[i];
    __half2 a = {__float2half(v.x), __float2half(v.y)};
    __half2 b = {__float2half(v.z), __float2half(v.w)};
    reinterpret_cast<__half2*>(g_wf)[i * 2 + 0] = a;
    reinterpret_cast<__half2*>(g_wf)[i * 2 + 1] = b;
}

// ---------------- 2) gating (vectorized) + fused x->fp16 conversion -------
__global__ void gating_kernel(const float* __restrict__ x,
                              const float* __restrict__ Wg,
                              const float* __restrict__ bg) {
    __shared__ float4 sWg4[NEXP * 256];     // 32 KB
    __shared__ float sbg[NEXP];
    int tid = threadIdx.x;
    for (int i = tid; i < NEXP * 256; i += 256)
        sWg4[i] = reinterpret_cast<const float4*>(Wg)[i];
    if (tid < NEXP) sbg[tid] = bg[tid];
    __syncthreads();

    int warp = tid >> 5, lane = tid & 31;
    int t = blockIdx.x * 8 + warp;
    const float4* xr4 = reinterpret_cast<const float4*>(x) + (size_t)t * 256;
    __half2* xo2 = reinterpret_cast<__half2*>(g_xf) + (size_t)t * 512;

    float acc[NEXP];
#pragma unroll
    for (int e = 0; e < NEXP; e++) acc[e] = 0.f;

#pragma unroll
    for (int it = 0; it < 8; it++) {
        int j4 = it * 32 + lane;
        float4 xv = xr4[j4];
        __half2 h0 = {__float2half(xv.x), __float2half(xv.y)};
        __half2 h1 = {__float2half(xv.z), __float2half(xv.w)};
        xo2[j4 * 2 + 0] = h0;
        xo2[j4 * 2 + 1] = h1;
#pragma unroll
        for (int e = 0; e < NEXP; e++) {
            float4 wv = sWg4[e * 256 + j4];
            acc[e] += xv.x * wv.x + xv.y * wv.y + xv.z * wv.z + xv.w * wv.w;
        }
    }
#pragma unroll
    for (int e = 0; e < NEXP; e++)
#pragma unroll
        for (int o = 16; o; o >>= 1) acc[e] += __shfl_xor_sync(0xffffffffu, acc[e], o);

    if (lane == 0) {
        float s[NEXP], m = -1e30f;
#pragma unroll
        for (int e = 0; e < NEXP; e++) { s[e] = acc[e] + sbg[e]; m = fmaxf(m, s[e]); }
        float p[NEXP], sum = 0.f;
#pragma unroll
        for (int e = 0; e < NEXP; e++) { p[e] = __expf(s[e] - m); sum += p[e]; }
        float inv = 1.f / sum;
#pragma unroll
        for (int e = 0; e < NEXP; e++) p[e] *= inv;
        int i0 = 0;
#pragma unroll
        for (int e = 1; e < NEXP; e++) if (p[e] > p[i0]) i0 = e;
        int i1 = -1;
#pragma unroll
        for (int e = 0; e < NEXP; e++) {
            if (e == i0) continue;
            if (i1 < 0 || p[e] > p[i1]) i1 = e;
        }
        g_topi[t] = i0 | (i1 << 8);
        g_w0[t] = p[i0];
        g_w1[t] = p[i1];
        atomicAdd(&g_cnt[i0], 1);
        atomicAdd(&g_cnt[i1], 1);
    }
}

// ---------------- 3) scatter (local prefix scan; no separate scan kernel) -
__global__ void scatter_kernel() {
    __shared__ int soff[NEXP];
    if (threadIdx.x == 0) {
        int o = 0;
#pragma unroll
        for (int e = 0; e < NEXP; e++) { soff[e] = o; o += g_cnt[e]; }
        if (blockIdx.x == 0) {          // publish for the GEMM kernel
            int o2 = 0;
#pragma unroll
            for (int e = 0; e < NEXP; e++) { g_off[e] = o2; o2 += g_cnt[e]; }
            g_off[NEXP] = o2;
        }
    }
    __syncthreads();
    int t = blockIdx.x * blockDim.x + threadIdx.x;
    int pk = g_topi[t];
    int i0 = pk & 0xff, i1 = (pk >> 8) & 0xff;
    int p0 = soff[i0] + atomicAdd(&g_cur2[i0], 1);
    g_tok[p0] = t; g_wt[p0] = g_w0[t]; g_slot0[t] = p0;
    int p1 = soff[i1] + atomicAdd(&g_cur2[i1], 1);
    g_tok[p1] = t; g_wt[p1] = g_w1[t]; g_slot1[t] = p1;
}

// ---------------- 4) grouped GEMM: KCHUNK=64, 3 stages, split loads -------
#define KCHUNK 64
#define NSTG 3
#define ROWB 144
#define STG_A 0
#define STG_B 18432
#define STG_SZ 36864
#define HDR 2048
#define SMEM_TOTAL (HDR + NSTG * STG_SZ)   // 112640 (x2 CTA = 225280 <= 228KB)

extern __shared__ __align__(1024) char dyn_smem[];

struct GArgs {
    uint32_t sbase;
    const int* stok;
    int wbase;     // e*DIM + col0
    int tid;
};

__device__ __forceinline__ void load_stage_A(const GArgs& a, int stage, int k0) {
    uint32_t st = a.sbase + HDR + stage * STG_SZ;
#pragma unroll
    for (int q = 0; q < 4; q++) {               // A: 128 rows x 8 16B-chunks
        int idx = q * 256 + a.tid;
        int row = idx >> 3, c = idx & 7;
        size_t src = (size_t)a.stok[row] * DIM + k0 + c * 8;
        cp16(st + STG_A + row * ROWB + c * 16, g_xf + src);
    }
}
__device__ __forceinline__ void load_stage_B(const GArgs& a, int stage, int k0) {
    uint32_t st = a.sbase + HDR + stage * STG_SZ;
#pragma unroll
    for (int q = 0; q < 4; q++) {               // B: 128 rows x 8 16B-chunks
        int idx = q * 256 + a.tid;
        int row = idx >> 3, c = idx & 7;
        size_t src = (size_t)(a.wbase + row) * DIM + k0 + c * 8;
        cp16(st + STG_B + row * ROWB + c * 16, g_wf + src);
    }
    CP_COMMIT();
}

// One K=16 step: 6 LDSM + 16 MMA. ks in 0..3 selects 32B column offset.
__device__ __forceinline__ void compute_kstep(uint32_t st, int m0, int n0, int lane,
                                              int ks, float acc[2][8][4]) {
    uint32_t a[2][4];
#pragma unroll
    for (int fi = 0; fi < 2; fi++) {
        uint32_t addr = st + STG_A + (uint32_t)(m0 + fi * 16 + (lane & 15)) * ROWB
                      + ks * 32 + ((lane >> 4) << 4);
        LDSM4(a[fi], addr);
    }
#pragma unroll
    for (int fj2 = 0; fj2 < 4; fj2++) {
        uint32_t b[4];
        uint32_t addr = st + STG_B
            + (uint32_t)(n0 + fj2 * 16 + (((lane >> 4) & 1) << 3) + (lane & 7)) * ROWB
            + ks * 32 + (((lane >> 3) & 1) << 4);
        LDSM4(b, addr);
        MMA16816(acc[0][2 * fj2 + 0], a[0], b[0], b[1]);
        MMA16816(acc[0][2 * fj2 + 1], a[0], b[2], b[3]);
        MMA16816(acc[1][2 * fj2 + 0], a[1], b[0], b[1]);
        MMA16816(acc[1][2 * fj2 + 1], a[1], b[2], b[3]);
    }
}

__global__ __launch_bounds__(256, 2)
void moe_gemm_mma(const float* __restrict__ bias) {
    int e = blockIdx.z;
    int base = g_off[e];
    int cnt = g_off[e + 1] - base;
    int row0 = blockIdx.y * 128;
    if (row0 >= cnt) return;
    int col0 = blockIdx.x * 128;

    int* stok = reinterpret_cast<int*>(dyn_smem);
    float* swt = reinterpret_cast<float*>(dyn_smem + 512);
    float* sbias = reinterpret_cast<float*>(dyn_smem + 1024);

    int tid = threadIdx.x;
    if (tid < 128) {
        int p = row0 + tid;
        int pc = p < cnt ? p : cnt - 1;
        stok[tid] = g_tok[base + pc];
        swt[tid] = (p < cnt) ? g_wt[base + p] : 0.f;
    }
    if (tid < 32)
        reinterpret_cast<float4*>(sbias)[tid] =
            reinterpret_cast<const float4*>(bias + e * DIM + col0)[tid];
    __syncthreads();

    uint32_t sbase = smem_u32(dyn_smem);
    GArgs ga{sbase, stok, e * DIM + col0, tid};

    load_stage_A(ga, 0, 0);          load_stage_B(ga, 0, 0);           // group 0
    load_stage_A(ga, 1, KCHUNK);     load_stage_B(ga, 1, KCHUNK);      // group 1

    int lane = tid & 31, wid = tid >> 5;
    int m0 = (wid & 3) * 32, n0 = (wid >> 2) * 64;

    float acc[2][8][4];
#pragma unroll
    for (int i = 0; i < 2; i++)
#pragma unroll
        for (int j = 0; j < 8; j++)
#pragma unroll
            for (int k = 0; k < 4; k++) acc[i][j][k] = 0.f;

    const int NIT = DIM / KCHUNK;   // 16
    for (int i = 0; i < NIT; i++) {
        int s = i % 3;
        // groups committed so far: 2 + i. wait_group 1 -> groups 0..i done,
        // so stage s (=group i) is resident.
        asm volatile("cp.async.wait_group 1;" ::: "memory");
        __syncthreads();
        uint32_t stg = sbase + HDR + s * STG_SZ;
        int nstage = (i + 2) % 3;       // == (i-1)%3: all warps done reading it
        bool doload = (i + 2) < NIT;
        compute_kstep(stg, m0, n0, lane, 0, acc);
        if (doload) load_stage_A(ga, nstage, (i + 2) * KCHUNK);
        compute_kstep(stg, m0, n0, lane, 1, acc);
        if (doload) load_stage_B(ga, nstage, (i + 2) * KCHUNK);
        else CP_COMMIT();               // tail: keep group arithmetic exact
        compute_kstep(stg, m0, n0, lane, 2, acc);
        compute_kstep(stg, m0, n0, lane, 3, acc);
    }

    // epilogue: scaled (+bias) fp16 write to slot scratch
    int tq = lane >> 2, tr = lane & 3;
#pragma unroll
    for (int fi = 0; fi < 2; fi++) {
#pragma unroll
        for (int h = 0; h < 2; h++) {
            int m = m0 + fi * 16 + h * 8 + tq;
            int gr = row0 + m;
            if (gr < cnt) {
                float w = swt[m];
                __half* orow = g_scr + (size_t)(base + gr) * DIM + col0;
#pragma unroll
                for (int fj = 0; fj < 8; fj++) {
                    int cn = n0 + fj * 8 + tr * 2;
                    float vx = w * (acc[fi][fj][h * 2 + 0] + sbias[cn]);
                    float vy = w * (acc[fi][fj][h * 2 + 1] + sbias[cn + 1]);
                    *reinterpret_cast<__half2*>(orow + cn) = __floats2half2_rn(vx, vy);
                }
            }
        }
    }
}

// ---------------- 5) combine (fp16 scr -> fp32 out) ----------------
__global__ void combine_kernel(float* __restrict__ out) {
    int idx = blockIdx.x * 256 + threadIdx.x;   // 8-half chunk index
    int t = idx >> 7;                            // 128 chunks per token
    int c = idx & 127;
    const uint4* s4 = reinterpret_cast<const uint4*>(g_scr);
    uint4 a = s4[(size_t)g_slot0[t] * 128 + c];
    uint4 b = s4[(size_t)g_slot1[t] * 128 + c];
    const __half2* ah = reinterpret_cast<const __half2*>(&a);
    const __half2* bh = reinterpret_cast<const __half2*>(&b);
    float4 o0, o1;
    float2 p0 = __half22float2(ah[0]), q0 = __half22float2(bh[0]);
    float2 p1 = __half22float2(ah[1]), q1 = __half22float2(bh[1]);
    float2 p2 = __half22float2(ah[2]), q2 = __half22float2(bh[2]);
    float2 p3 = __half22float2(ah[3]), q3 = __half22float2(bh[3]);
    o0.x = p0.x + q0.x; o0.y = p0.y + q0.y; o0.z = p1.x + q1.x; o0.w = p1.y + q1.y;
    o1.x = p2.x + q2.x; o1.y = p2.y + q2.y; o1.z = p3.x + q3.x; o1.w = p3.y + q3.y;
    float4* out4 = reinterpret_cast<float4*>(out);
    out4[idx * 2 + 0] = o0;
    out4[idx * 2 + 1] = o1;
}

// ---------------------------------------------------------------------------
extern "C" void kernel_launch(void* const* d_in, const int* in_sizes, int n_in,
                              void* d_out, int out_size) {
    const float* x  = (const float*)d_in[0];
    const float* Wg = (const float*)d_in[1];
    const float* bg = (const float*)d_in[2];
    const float* W  = (const float*)d_in[3];
    const float* b  = (const float*)d_in[4];
    float* out = (float*)d_out;

    cudaFuncSetAttribute(moe_gemm_mma, cudaFuncAttributeMaxDynamicSharedMemorySize,
                         SMEM_TOTAL);

    conv_w_kernel<<<(NEXP * DIM * DIM) / (4 * 256), 256>>>(W);
    gating_kernel<<<NTOK / 8, 256>>>(x, Wg, bg);
    scatter_kernel<<<NTOK / 256, 256>>>();
    moe_gemm_mma<<<dim3(8, 512, 8), 256, SMEM_TOTAL>>>(b);
    combine_kernel<<<(NTOK * DIM) / (8 * 256), 256>>>(out);
}

// round 14
// speedup vs baseline: 1.1012x; 1.0148x over previous
#include <cuda_runtime.h>
#include <cuda_fp16.h>
#include <cstdint>

#define NTOK 32768
#define DIM 1024
#define NEXP 8
#define NROWS (NTOK * 2)

// ---------------- device scratch (no allocation allowed) ----------------
__device__ int   g_cnt[NEXP];
__device__ int   g_off[NEXP + 1];
__device__ int   g_cur2[NEXP];
__device__ int   g_tok[NROWS];
__device__ float g_wt[NROWS];
__device__ int   g_topi[NTOK];
__device__ float g_w0[NTOK];
__device__ float g_w1[NTOK];
__device__ int   g_slot0[NTOK];
__device__ int   g_slot1[NTOK];
__device__ __half g_xf[(size_t)NTOK * DIM];            // fp16 x
__device__ __half g_wf[(size_t)NEXP * DIM * DIM];      // fp16 W
__device__ __half g_scr[(size_t)NROWS * DIM];          // fp16 slot scratch (128 MB)

// ---------------- PTX helpers (base-target PTX only) ----------------
__device__ __forceinline__ uint32_t smem_u32(const void* p) {
    uint32_t a;
    asm("{ .reg .u64 t; cvta.to.shared.u64 t, %1; cvt.u32.u64 %0, t; }" : "=r"(a) : "l"(p));
    return a;
}
__device__ __forceinline__ void cp16(uint32_t dst, const void* src) {
    asm volatile("cp.async.cg.shared.global [%0], [%1], 16;" :: "r"(dst), "l"(src));
}
#define CP_COMMIT() asm volatile("cp.async.commit_group;" ::: "memory")

#define LDSM4(r, addr) \
    asm volatile("ldmatrix.sync.aligned.m8n8.x4.shared.b16 {%0,%1,%2,%3}, [%4];" \
        : "=r"((r)[0]), "=r"((r)[1]), "=r"((r)[2]), "=r"((r)[3]) : "r"(addr))

#define MMA16816(d, a, b0, b1) \
    asm volatile("mma.sync.aligned.m16n8k16.row.col.f32.f16.f16.f32 " \
        "{%0,%1,%2,%3},{%4,%5,%6,%7},{%8,%9},{%0,%1,%2,%3};" \
        : "+f"((d)[0]), "+f"((d)[1]), "+f"((d)[2]), "+f"((d)[3]) \
        : "r"((a)[0]), "r"((a)[1]), "r"((a)[2]), "r"((a)[3]), "r"(b0), "r"(b1))

// ---------------- 1) convert W fp32 -> fp16 (+ zero counters, folded) -----
__global__ void conv_w_kernel(const float* __restrict__ W) {
    if (blockIdx.x == 0 && threadIdx.x < NEXP) {
        g_cnt[threadIdx.x] = 0;
        g_cur2[threadIdx.x] = 0;
    }
    int i = blockIdx.x * 256 + threadIdx.x;
    float4 v = reinterpret_cast<const float4*>(W)[i];
    __half2 a = {__float2half(v.x), __float2half(v.y)};
    __half2 b = {__float2half(v.z), __float2half(v.w)};
    reinterpret_cast<__half2*>(g_wf)[i * 2 + 0] = a;
    reinterpret_cast<__half2*>(g_wf)[i * 2 + 1] = b;
}

// ---------------- 2) gating (vectorized) + fused x->fp16 conversion -------
__global__ void gating_kernel(const float* __restrict__ x,
                              const float* __restrict__ Wg,
                              const float* __restrict__ bg) {
    __shared__ float4 sWg4[NEXP * 256];     // 32 KB
    __shared__ float sbg[NEXP];
    int tid = threadIdx.x;
    for (int i = tid; i < NEXP * 256; i += 256)
        sWg4[i] = reinterpret_cast<const float4*>(Wg)[i];
    if (tid < NEXP) sbg[tid] = bg[tid];
    __syncthreads();

    int warp = tid >> 5, lane = tid & 31;
    int t = blockIdx.x * 8 + warp;
    const float4* xr4 = reinterpret_cast<const float4*>(x) + (size_t)t * 256;
    __half2* xo2 = reinterpret_cast<__half2*>(g_xf) + (size_t)t * 512;

    float acc[NEXP];
#pragma unroll
    for (int e = 0; e < NEXP; e++) acc[e] = 0.f;

#pragma unroll
    for (int it = 0; it < 8; it++) {
        int j4 = it * 32 + lane;
        float4 xv = xr4[j4];
        __half2 h0 = {__float2half(xv.x), __float2half(xv.y)};
        __half2 h1 = {__float2half(xv.z), __float2half(xv.w)};
        xo2[j4 * 2 + 0] = h0;
        xo2[j4 * 2 + 1] = h1;
#pragma unroll
        for (int e = 0; e < NEXP; e++) {
            float4 wv = sWg4[e * 256 + j4];
            acc[e] += xv.x * wv.x + xv.y * wv.y + xv.z * wv.z + xv.w * wv.w;
        }
    }
#pragma unroll
    for (int e = 0; e < NEXP; e++)
#pragma unroll
        for (int o = 16; o; o >>= 1) acc[e] += __shfl_xor_sync(0xffffffffu, acc[e], o);

    if (lane == 0) {
        float s[NEXP], m = -1e30f;
#pragma unroll
        for (int e = 0; e < NEXP; e++) { s[e] = acc[e] + sbg[e]; m = fmaxf(m, s[e]); }
        float p[NEXP], sum = 0.f;
#pragma unroll
        for (int e = 0; e < NEXP; e++) { p[e] = __expf(s[e] - m); sum += p[e]; }
        float inv = 1.f / sum;
#pragma unroll
        for (int e = 0; e < NEXP; e++) p[e] *= inv;
        int i0 = 0;
#pragma unroll
        for (int e = 1; e < NEXP; e++) if (p[e] > p[i0]) i0 = e;
        int i1 = -1;
#pragma unroll
        for (int e = 0; e < NEXP; e++) {
            if (e == i0) continue;
            if (i1 < 0 || p[e] > p[i1]) i1 = e;
        }
        g_topi[t] = i0 | (i1 << 8);
        g_w0[t] = p[i0];
        g_w1[t] = p[i1];
        atomicAdd(&g_cnt[i0], 1);
        atomicAdd(&g_cnt[i1], 1);
    }
}

// ---------------- 3) scatter (local prefix scan; no separate scan kernel) -
__global__ void scatter_kernel() {
    __shared__ int soff[NEXP];
    if (threadIdx.x == 0) {
        int o = 0;
#pragma unroll
        for (int e = 0; e < NEXP; e++) { soff[e] = o; o += g_cnt[e]; }
        if (blockIdx.x == 0) {          // publish for the GEMM kernel
            int o2 = 0;
#pragma unroll
            for (int e = 0; e < NEXP; e++) { g_off[e] = o2; o2 += g_cnt[e]; }
            g_off[NEXP] = o2;
        }
    }
    __syncthreads();
    int t = blockIdx.x * blockDim.x + threadIdx.x;
    int pk = g_topi[t];
    int i0 = pk & 0xff, i1 = (pk >> 8) & 0xff;
    int p0 = soff[i0] + atomicAdd(&g_cur2[i0], 1);
    g_tok[p0] = t; g_wt[p0] = g_w0[t]; g_slot0[t] = p0;
    int p1 = soff[i1] + atomicAdd(&g_cur2[i1], 1);
    g_tok[p1] = t; g_wt[p1] = g_w1[t]; g_slot1[t] = p1;
}

// ---------------- 4) grouped GEMM: KCHUNK=64, 3 stages, 4-way split loads -
#define KCHUNK 64
#define NSTG 3
#define ROWB 144
#define STG_A 0
#define STG_B 18432
#define STG_SZ 36864
#define HDR 2048
#define SMEM_TOTAL (HDR + NSTG * STG_SZ)   // 112640 (x2 CTA = 225280 <= 228KB)

extern __shared__ __align__(1024) char dyn_smem[];

struct GArgs {
    uint32_t sbase;
    const int* stok;
    int wbase;     // e*DIM + col0
    int tid;
};

// half in {0,1}: two 16B-chunk quarters of the A plane (2 cp.async/thread)
__device__ __forceinline__ void load_A_half(const GArgs& a, int stage, int k0, int half) {
    uint32_t st = a.sbase + HDR + stage * STG_SZ;
#pragma unroll
    for (int q = 0; q < 2; q++) {
        int idx = (half * 2 + q) * 256 + a.tid;
        int row = idx >> 3, c = idx & 7;
        size_t src = (size_t)a.stok[row] * DIM + k0 + c * 8;
        cp16(st + STG_A + row * ROWB + c * 16, g_xf + src);
    }
}
__device__ __forceinline__ void load_B_half(const GArgs& a, int stage, int k0, int half) {
    uint32_t st = a.sbase + HDR + stage * STG_SZ;
#pragma unroll
    for (int q = 0; q < 2; q++) {
        int idx = (half * 2 + q) * 256 + a.tid;
        int row = idx >> 3, c = idx & 7;
        size_t src = (size_t)(a.wbase + row) * DIM + k0 + c * 8;
        cp16(st + STG_B + row * ROWB + c * 16, g_wf + src);
    }
}

// One K=16 step: 6 LDSM + 16 MMA. ks in 0..3 selects 32B column offset.
__device__ __forceinline__ void compute_kstep(uint32_t st, int m0, int n0, int lane,
                                              int ks, float acc[2][8][4]) {
    uint32_t a[2][4];
#pragma unroll
    for (int fi = 0; fi < 2; fi++) {
        uint32_t addr = st + STG_A + (uint32_t)(m0 + fi * 16 + (lane & 15)) * ROWB
                      + ks * 32 + ((lane >> 4) << 4);
        LDSM4(a[fi], addr);
    }
#pragma unroll
    for (int fj2 = 0; fj2 < 4; fj2++) {
        uint32_t b[4];
        uint32_t addr = st + STG_B
            + (uint32_t)(n0 + fj2 * 16 + (((lane >> 4) & 1) << 3) + (lane & 7)) * ROWB
            + ks * 32 + (((lane >> 3) & 1) << 4);
        LDSM4(b, addr);
        MMA16816(acc[0][2 * fj2 + 0], a[0], b[0], b[1]);
        MMA16816(acc[0][2 * fj2 + 1], a[0], b[2], b[3]);
        MMA16816(acc[1][2 * fj2 + 0], a[1], b[0], b[1]);
        MMA16816(acc[1][2 * fj2 + 1], a[1], b[2], b[3]);
    }
}

__global__ __launch_bounds__(256, 2)
void moe_gemm_mma(const float* __restrict__ bias) {
    int e = blockIdx.z;
    int base = g_off[e];
    int cnt = g_off[e + 1] - base;
    int row0 = blockIdx.y * 128;
    if (row0 >= cnt) return;
    int col0 = blockIdx.x * 128;

    int* stok = reinterpret_cast<int*>(dyn_smem);
    float* swt = reinterpret_cast<float*>(dyn_smem + 512);
    float* sbias = reinterpret_cast<float*>(dyn_smem + 1024);

    int tid = threadIdx.x;
    if (tid < 128) {
        int p = row0 + tid;
        int pc = p < cnt ? p : cnt - 1;
        stok[tid] = g_tok[base + pc];
        swt[tid] = (p < cnt) ? g_wt[base + p] : 0.f;
    }
    if (tid < 32)
        reinterpret_cast<float4*>(sbias)[tid] =
            reinterpret_cast<const float4*>(bias + e * DIM + col0)[tid];
    __syncthreads();

    uint32_t sbase = smem_u32(dyn_smem);
    GArgs ga{sbase, stok, e * DIM + col0, tid};

    // prologue: stages 0 and 1 (one commit group each)
    load_A_half(ga, 0, 0, 0);      load_A_half(ga, 0, 0, 1);
    load_B_half(ga, 0, 0, 0);      load_B_half(ga, 0, 0, 1);      CP_COMMIT();
    load_A_half(ga, 1, KCHUNK, 0); load_A_half(ga, 1, KCHUNK, 1);
    load_B_half(ga, 1, KCHUNK, 0); load_B_half(ga, 1, KCHUNK, 1); CP_COMMIT();

    int lane = tid & 31, wid = tid >> 5;
    int m0 = (wid & 3) * 32, n0 = (wid >> 2) * 64;

    float acc[2][8][4];
#pragma unroll
    for (int i = 0; i < 2; i++)
#pragma unroll
        for (int j = 0; j < 8; j++)
#pragma unroll
            for (int k = 0; k < 4; k++) acc[i][j][k] = 0.f;

    const int NIT = DIM / KCHUNK;   // 16
    for (int i = 0; i < NIT; i++) {
        int s = i % 3;
        // committed groups before this wait: 2 + i; wait_group 1 -> groups
        // 0..i complete, so stage s (= group i) is resident.
        asm volatile("cp.async.wait_group 1;" ::: "memory");
        __syncthreads();
        uint32_t stg = sbase + HDR + s * STG_SZ;
        int nstage = (i + 2) % 3;       // == (i-1)%3: all warps done reading it
        bool doload = (i + 2) < NIT;
        int nk0 = (i + 2) * KCHUNK;
        // 4-way interleave: tiny LSU bursts in the shadow of each kstep's MMAs
        compute_kstep(stg, m0, n0, lane, 0, acc);
        if (doload) load_A_half(ga, nstage, nk0, 0);
        compute_kstep(stg, m0, n0, lane, 1, acc);
        if (doload) load_A_half(ga, nstage, nk0, 1);
        compute_kstep(stg, m0, n0, lane, 2, acc);
        if (doload) load_B_half(ga, nstage, nk0, 0);
        compute_kstep(stg, m0, n0, lane, 3, acc);
        if (doload) load_B_half(ga, nstage, nk0, 1);
        CP_COMMIT();                    // exactly one group per iteration
    }

    // epilogue: scaled (+bias) fp16 write to slot scratch
    int tq = lane >> 2, tr = lane & 3;
#pragma unroll
    for (int fi = 0; fi < 2; fi++) {
#pragma unroll
        for (int h = 0; h < 2; h++) {
            int m = m0 + fi * 16 + h * 8 + tq;
            int gr = row0 + m;
            if (gr < cnt) {
                float w = swt[m];
                __half* orow = g_scr + (size_t)(base + gr) * DIM + col0;
#pragma unroll
                for (int fj = 0; fj < 8; fj++) {
                    int cn = n0 + fj * 8 + tr * 2;
                    float vx = w * (acc[fi][fj][h * 2 + 0] + sbias[cn]);
                    float vy = w * (acc[fi][fj][h * 2 + 1] + sbias[cn + 1]);
                    *reinterpret_cast<__half2*>(orow + cn) = __floats2half2_rn(vx, vy);
                }
            }
        }
    }
}

// ---------------- 5) combine (fp16 scr -> fp32 out) ----------------
__global__ void combine_kernel(float* __restrict__ out) {
    int idx = blockIdx.x * 256 + threadIdx.x;   // 8-half chunk index
    int t = idx >> 7;                            // 128 chunks per token
    int c = idx & 127;
    const uint4* s4 = reinterpret_cast<const uint4*>(g_scr);
    uint4 a = s4[(size_t)g_slot0[t] * 128 + c];
    uint4 b = s4[(size_t)g_slot1[t] * 128 + c];
    const __half2* ah = reinterpret_cast<const __half2*>(&a);
    const __half2* bh = reinterpret_cast<const __half2*>(&b);
    float4 o0, o1;
    float2 p0 = __half22float2(ah[0]), q0 = __half22float2(bh[0]);
    float2 p1 = __half22float2(ah[1]), q1 = __half22float2(bh[1]);
    float2 p2 = __half22float2(ah[2]), q2 = __half22float2(bh[2]);
    float2 p3 = __half22float2(ah[3]), q3 = __half22float2(bh[3]);
    o0.x = p0.x + q0.x; o0.y = p0.y + q0.y; o0.z = p1.x + q1.x; o0.w = p1.y + q1.y;
    o1.x = p2.x + q2.x; o1.y = p2.y + q2.y; o1.z = p3.x + q3.x; o1.w = p3.y + q3.y;
    float4* out4 = reinterpret_cast<float4*>(out);
    out4[idx * 2 + 0] = o0;
    out4[idx * 2 + 1] = o1;
}

// ---------------------------------------------------------------------------
extern "C" void kernel_launch(void* const* d_in, const int* in_sizes, int n_in,
                              void* d_out, int out_size) {
    const float* x  = (const float*)d_in[0];
    const float* Wg = (const float*)d_in[1];
    const float* bg = (const float*)d_in[2];
    const float* W  = (const float*)d_in[3];
    const float* b  = (const float*)d_in[4];
    float* out = (float*)d_out;

    cudaFuncSetAttribute(moe_gemm_mma, cudaFuncAttributeMaxDynamicSharedMemorySize,
                         SMEM_TOTAL);

    conv_w_kernel<<<(NEXP * DIM * DIM) / (4 * 256), 256>>>(W);
    gating_kernel<<<NTOK / 8, 256>>>(x, Wg, bg);
    scatter_kernel<<<NTOK / 256, 256>>>();
    moe_gemm_mma<<<dim3(8, 512, 8), 256, SMEM_TOTAL>>>(b);
    combine_kernel<<<(NTOK * DIM) / (8 * 256), 256>>>(out);
}

// round 15
// speedup vs baseline: 1.1597x; 1.0532x over previous
#include <cuda_runtime.h>
#include <cuda_fp16.h>
#include <cstdint>

#define NTOK 32768
#define DIM 1024
#define NEXP 8
#define NROWS (NTOK * 2)

// ---------------- device scratch (no allocation allowed) ----------------
__device__ int   g_cnt[NEXP];
__device__ int   g_off[NEXP + 1];
__device__ int   g_cur2[NEXP];
__device__ int   g_tok[NROWS];
__device__ float g_wt[NROWS];
__device__ int   g_topi[NTOK];
__device__ float g_w0[NTOK];
__device__ float g_w1[NTOK];
__device__ int   g_slot0[NTOK];
__device__ int   g_slot1[NTOK];
__device__ __half g_xf[(size_t)NTOK * DIM];            // fp16 x
__device__ __half g_wf[(size_t)NEXP * DIM * DIM];      // fp16 W
__device__ __half g_scr[(size_t)NROWS * DIM];          // fp16 slot scratch (128 MB)

// ---------------- PTX helpers (base-target PTX only) ----------------
__device__ __forceinline__ uint32_t smem_u32(const void* p) {
    uint32_t a;
    asm("{ .reg .u64 t; cvta.to.shared.u64 t, %1; cvt.u32.u64 %0, t; }" : "=r"(a) : "l"(p));
    return a;
}
__device__ __forceinline__ void cp16(uint32_t dst, const void* src) {
    asm volatile("cp.async.cg.shared.global [%0], [%1], 16;" :: "r"(dst), "l"(src));
}
#define CP_COMMIT() asm volatile("cp.async.commit_group;" ::: "memory")

#define LDSM4(r, addr) \
    asm volatile("ldmatrix.sync.aligned.m8n8.x4.shared.b16 {%0,%1,%2,%3}, [%4];" \
        : "=r"((r)[0]), "=r"((r)[1]), "=r"((r)[2]), "=r"((r)[3]) : "r"(addr))

#define MMA16816(d, a, b0, b1) \
    asm volatile("mma.sync.aligned.m16n8k16.row.col.f32.f16.f16.f32 " \
        "{%0,%1,%2,%3},{%4,%5,%6,%7},{%8,%9},{%0,%1,%2,%3};" \
        : "+f"((d)[0]), "+f"((d)[1]), "+f"((d)[2]), "+f"((d)[3]) \
        : "r"((a)[0]), "r"((a)[1]), "r"((a)[2]), "r"((a)[3]), "r"(b0), "r"(b1))

// ---------------- 1) convert W fp32 -> fp16 (+ zero counters, folded) -----
__global__ void conv_w_kernel(const float* __restrict__ W) {
    if (blockIdx.x == 0 && threadIdx.x < NEXP) {
        g_cnt[threadIdx.x] = 0;
        g_cur2[threadIdx.x] = 0;
    }
    int i = blockIdx.x * 256 + threadIdx.x;
    float4 v = reinterpret_cast<const float4*>(W)[i];
    __half2 a = {__float2half(v.x), __float2half(v.y)};
    __half2 b = {__float2half(v.z), __float2half(v.w)};
    reinterpret_cast<__half2*>(g_wf)[i * 2 + 0] = a;
    reinterpret_cast<__half2*>(g_wf)[i * 2 + 1] = b;
}

// ---------------- 2) gating (vectorized) + fused x->fp16 conversion -------
__global__ void gating_kernel(const float* __restrict__ x,
                              const float* __restrict__ Wg,
                              const float* __restrict__ bg) {
    __shared__ float4 sWg4[NEXP * 256];     // 32 KB
    __shared__ float sbg[NEXP];
    int tid = threadIdx.x;
    for (int i = tid; i < NEXP * 256; i += 256)
        sWg4[i] = reinterpret_cast<const float4*>(Wg)[i];
    if (tid < NEXP) sbg[tid] = bg[tid];
    __syncthreads();

    int warp = tid >> 5, lane = tid & 31;
    int t = blockIdx.x * 8 + warp;
    const float4* xr4 = reinterpret_cast<const float4*>(x) + (size_t)t * 256;
    __half2* xo2 = reinterpret_cast<__half2*>(g_xf) + (size_t)t * 512;

    float acc[NEXP];
#pragma unroll
    for (int e = 0; e < NEXP; e++) acc[e] = 0.f;

#pragma unroll
    for (int it = 0; it < 8; it++) {
        int j4 = it * 32 + lane;
        float4 xv = xr4[j4];
        __half2 h0 = {__float2half(xv.x), __float2half(xv.y)};
        __half2 h1 = {__float2half(xv.z), __float2half(xv.w)};
        xo2[j4 * 2 + 0] = h0;
        xo2[j4 * 2 + 1] = h1;
#pragma unroll
        for (int e = 0; e < NEXP; e++) {
            float4 wv = sWg4[e * 256 + j4];
            acc[e] += xv.x * wv.x + xv.y * wv.y + xv.z * wv.z + xv.w * wv.w;
        }
    }
#pragma unroll
    for (int e = 0; e < NEXP; e++)
#pragma unroll
        for (int o = 16; o; o >>= 1) acc[e] += __shfl_xor_sync(0xffffffffu, acc[e], o);

    if (lane == 0) {
        float s[NEXP], m = -1e30f;
#pragma unroll
        for (int e = 0; e < NEXP; e++) { s[e] = acc[e] + sbg[e]; m = fmaxf(m, s[e]); }
        float p[NEXP], sum = 0.f;
#pragma unroll
        for (int e = 0; e < NEXP; e++) { p[e] = __expf(s[e] - m); sum += p[e]; }
        float inv = 1.f / sum;
#pragma unroll
        for (int e = 0; e < NEXP; e++) p[e] *= inv;
        int i0 = 0;
#pragma unroll
        for (int e = 1; e < NEXP; e++) if (p[e] > p[i0]) i0 = e;
        int i1 = -1;
#pragma unroll
        for (int e = 0; e < NEXP; e++) {
            if (e == i0) continue;
            if (i1 < 0 || p[e] > p[i1]) i1 = e;
        }
        g_topi[t] = i0 | (i1 << 8);
        g_w0[t] = p[i0];
        g_w1[t] = p[i1];
        atomicAdd(&g_cnt[i0], 1);
        atomicAdd(&g_cnt[i1], 1);
    }
}

// ---------------- 3) scatter (local prefix scan; no separate scan kernel) -
__global__ void scatter_kernel() {
    __shared__ int soff[NEXP];
    if (threadIdx.x == 0) {
        int o = 0;
#pragma unroll
        for (int e = 0; e < NEXP; e++) { soff[e] = o; o += g_cnt[e]; }
        if (blockIdx.x == 0) {          // publish for the GEMM kernel
            int o2 = 0;
#pragma unroll
            for (int e = 0; e < NEXP; e++) { g_off[e] = o2; o2 += g_cnt[e]; }
            g_off[NEXP] = o2;
        }
    }
    __syncthreads();
    int t = blockIdx.x * blockDim.x + threadIdx.x;
    int pk = g_topi[t];
    int i0 = pk & 0xff, i1 = (pk >> 8) & 0xff;
    int p0 = soff[i0] + atomicAdd(&g_cur2[i0], 1);
    g_tok[p0] = t; g_wt[p0] = g_w0[t]; g_slot0[t] = p0;
    int p1 = soff[i1] + atomicAdd(&g_cur2[i1], 1);
    g_tok[p1] = t; g_wt[p1] = g_w1[t]; g_slot1[t] = p1;
}

// ---------------- 4) grouped GEMM: KCHUNK=64, 3 stages, unrolled mainloop -
#define KCHUNK 64
#define NSTG 3
#define ROWB 144
#define STG_A 0
#define STG_B 18432
#define STG_SZ 36864
#define HDR 2048
#define SMEM_TOTAL (HDR + NSTG * STG_SZ)   // 112640 (x2 CTA = 225280 <= 228KB)

extern __shared__ __align__(1024) char dyn_smem[];

struct GArgs {
    uint32_t sbase;
    const int* stok;
    int wbase;     // e*DIM + col0
    int tid;
};

// half in {0,1}: two 16B-chunk quarters of the A plane (2 cp.async/thread)
__device__ __forceinline__ void load_A_half(const GArgs& a, int stage, int k0, int half) {
    uint32_t st = a.sbase + HDR + stage * STG_SZ;
#pragma unroll
    for (int q = 0; q < 2; q++) {
        int idx = (half * 2 + q) * 256 + a.tid;
        int row = idx >> 3, c = idx & 7;
        size_t src = (size_t)a.stok[row] * DIM + k0 + c * 8;
        cp16(st + STG_A + row * ROWB + c * 16, g_xf + src);
    }
}
__device__ __forceinline__ void load_B_half(const GArgs& a, int stage, int k0, int half) {
    uint32_t st = a.sbase + HDR + stage * STG_SZ;
#pragma unroll
    for (int q = 0; q < 2; q++) {
        int idx = (half * 2 + q) * 256 + a.tid;
        int row = idx >> 3, c = idx & 7;
        size_t src = (size_t)(a.wbase + row) * DIM + k0 + c * 8;
        cp16(st + STG_B + row * ROWB + c * 16, g_wf + src);
    }
}

// One K=16 step: 6 LDSM + 16 MMA. ks in 0..3 selects 32B column offset.
__device__ __forceinline__ void compute_kstep(uint32_t st, int m0, int n0, int lane,
                                              int ks, float acc[2][8][4]) {
    uint32_t a[2][4];
#pragma unroll
    for (int fi = 0; fi < 2; fi++) {
        uint32_t addr = st + STG_A + (uint32_t)(m0 + fi * 16 + (lane & 15)) * ROWB
                      + ks * 32 + ((lane >> 4) << 4);
        LDSM4(a[fi], addr);
    }
#pragma unroll
    for (int fj2 = 0; fj2 < 4; fj2++) {
        uint32_t b[4];
        uint32_t addr = st + STG_B
            + (uint32_t)(n0 + fj2 * 16 + (((lane >> 4) & 1) << 3) + (lane & 7)) * ROWB
            + ks * 32 + (((lane >> 3) & 1) << 4);
        LDSM4(b, addr);
        MMA16816(acc[0][2 * fj2 + 0], a[0], b[0], b[1]);
        MMA16816(acc[0][2 * fj2 + 1], a[0], b[2], b[3]);
        MMA16816(acc[1][2 * fj2 + 0], a[1], b[0], b[1]);
        MMA16816(acc[1][2 * fj2 + 1], a[1], b[2], b[3]);
    }
}

__global__ __launch_bounds__(256, 2)
void moe_gemm_mma(const float* __restrict__ bias) {
    int e = blockIdx.z;
    int base = g_off[e];
    int cnt = g_off[e + 1] - base;
    int row0 = blockIdx.y * 128;
    if (row0 >= cnt) return;
    int col0 = blockIdx.x * 128;

    int* stok = reinterpret_cast<int*>(dyn_smem);
    float* swt = reinterpret_cast<float*>(dyn_smem + 512);
    float* sbias = reinterpret_cast<float*>(dyn_smem + 1024);

    int tid = threadIdx.x;
    if (tid < 128) {
        int p = row0 + tid;
        int pc = p < cnt ? p : cnt - 1;
        stok[tid] = g_tok[base + pc];
        swt[tid] = (p < cnt) ? g_wt[base + p] : 0.f;
    }
    if (tid < 32)
        reinterpret_cast<float4*>(sbias)[tid] =
            reinterpret_cast<const float4*>(bias + e * DIM + col0)[tid];
    __syncthreads();

    uint32_t sbase = smem_u32(dyn_smem);
    GArgs ga{sbase, stok, e * DIM + col0, tid};

    // prologue: stages 0 and 1 (one commit group each)
    load_A_half(ga, 0, 0, 0);      load_A_half(ga, 0, 0, 1);
    load_B_half(ga, 0, 0, 0);      load_B_half(ga, 0, 0, 1);      CP_COMMIT();
    load_A_half(ga, 1, KCHUNK, 0); load_A_half(ga, 1, KCHUNK, 1);
    load_B_half(ga, 1, KCHUNK, 0); load_B_half(ga, 1, KCHUNK, 1); CP_COMMIT();

    int lane = tid & 31, wid = tid >> 5;
    int m0 = (wid & 3) * 32, n0 = (wid >> 2) * 64;

    float acc[2][8][4];
#pragma unroll
    for (int i = 0; i < 2; i++)
#pragma unroll
        for (int j = 0; j < 8; j++)
#pragma unroll
            for (int k = 0; k < 4; k++) acc[i][j][k] = 0.f;

    const int NIT = DIM / KCHUNK;   // 16
#pragma unroll
    for (int i = 0; i < NIT; i++) {
        int s = i % 3;               // constant after full unroll
        // committed groups before this wait: 2 + i; wait_group 1 -> groups
        // 0..i complete, so stage s (= group i) is resident.
        asm volatile("cp.async.wait_group 1;" ::: "memory");
        __syncthreads();
        uint32_t stg = sbase + HDR + s * STG_SZ;
        int nstage = (i + 2) % 3;       // == (i-1)%3: all warps done reading it
        bool doload = (i + 2) < NIT;
        int nk0 = (i + 2) * KCHUNK;
        // 4-way interleave: tiny LSU bursts in the shadow of each kstep's MMAs
        compute_kstep(stg, m0, n0, lane, 0, acc);
        if (doload) load_A_half(ga, nstage, nk0, 0);
        compute_kstep(stg, m0, n0, lane, 1, acc);
        if (doload) load_A_half(ga, nstage, nk0, 1);
        compute_kstep(stg, m0, n0, lane, 2, acc);
        if (doload) load_B_half(ga, nstage, nk0, 0);
        compute_kstep(stg, m0, n0, lane, 3, acc);
        if (doload) load_B_half(ga, nstage, nk0, 1);
        CP_COMMIT();                    // exactly one group per iteration
    }

    // epilogue: scaled (+bias) fp16 write to slot scratch
    int tq = lane >> 2, tr = lane & 3;
#pragma unroll
    for (int fi = 0; fi < 2; fi++) {
#pragma unroll
        for (int h = 0; h < 2; h++) {
            int m = m0 + fi * 16 + h * 8 + tq;
            int gr = row0 + m;
            if (gr < cnt) {
                float w = swt[m];
                __half* orow = g_scr + (size_t)(base + gr) * DIM + col0;
#pragma unroll
                for (int fj = 0; fj < 8; fj++) {
                    int cn = n0 + fj * 8 + tr * 2;
                    float vx = w * (acc[fi][fj][h * 2 + 0] + sbias[cn]);
                    float vy = w * (acc[fi][fj][h * 2 + 1] + sbias[cn + 1]);
                    *reinterpret_cast<__half2*>(orow + cn) = __floats2half2_rn(vx, vy);
                }
            }
        }
    }
}

// ---------------- 5) combine (fp16 scr -> fp32 out) ----------------
__global__ void combine_kernel(float* __restrict__ out) {
    int idx = blockIdx.x * 256 + threadIdx.x;   // 8-half chunk index
    int t = idx >> 7;                            // 128 chunks per token
    int c = idx & 127;
    const uint4* s4 = reinterpret_cast<const uint4*>(g_scr);
    uint4 a = s4[(size_t)g_slot0[t] * 128 + c];
    uint4 b = s4[(size_t)g_slot1[t] * 128 + c];
    const __half2* ah = reinterpret_cast<const __half2*>(&a);
    const __half2* bh = reinterpret_cast<const __half2*>(&b);
    float4 o0, o1;
    float2 p0 = __half22float2(ah[0]), q0 = __half22float2(bh[0]);
    float2 p1 = __half22float2(ah[1]), q1 = __half22float2(bh[1]);
    float2 p2 = __half22float2(ah[2]), q2 = __half22float2(bh[2]);
    float2 p3 = __half22float2(ah[3]), q3 = __half22float2(bh[3]);
    o0.x = p0.x + q0.x; o0.y = p0.y + q0.y; o0.z = p1.x + q1.x; o0.w = p1.y + q1.y;
    o1.x = p2.x + q2.x; o1.y = p2.y + q2.y; o1.z = p3.x + q3.x; o1.w = p3.y + q3.y;
    float4* out4 = reinterpret_cast<float4*>(out);
    out4[idx * 2 + 0] = o0;
    out4[idx * 2 + 1] = o1;
}

// ---------------------------------------------------------------------------
extern "C" void kernel_launch(void* const* d_in, const int* in_sizes, int n_in,
                              void* d_out, int out_size) {
    const float* x  = (const float*)d_in[0];
    const float* Wg = (const float*)d_in[1];
    const float* bg = (const float*)d_in[2];
    const float* W  = (const float*)d_in[3];
    const float* b  = (const float*)d_in[4];
    float* out = (float*)d_out;

    cudaFuncSetAttribute(moe_gemm_mma, cudaFuncAttributeMaxDynamicSharedMemorySize,
                         SMEM_TOTAL);

    conv_w_kernel<<<(NEXP * DIM * DIM) / (4 * 256), 256>>>(W);
    gating_kernel<<<NTOK / 8, 256>>>(x, Wg, bg);
    scatter_kernel<<<NTOK / 256, 256>>>();
    moe_gemm_mma<<<dim3(8, 512, 8), 256, SMEM_TOTAL>>>(b);
    combine_kernel<<<(NTOK * DIM) / (8 * 256), 256>>>(out);
}

// round 16
// speedup vs baseline: 1.1627x; 1.0026x over previous
#include <cuda_runtime.h>
#include <cuda_fp16.h>
#include <cstdint>

#define NTOK 32768
#define DIM 1024
#define NEXP 8
#define NROWS (NTOK * 2)

// ---------------- device scratch (no allocation allowed) ----------------
__device__ int   g_cnt[NEXP];
__device__ int   g_off[NEXP + 1];
__device__ int   g_cur2[NEXP];
__device__ int   g_toff[NEXP + 1];   // row-tile prefix per expert
__device__ int   g_tick;             // persistent-GEMM ticket counter
__device__ int   g_tok[NROWS];
__device__ float g_wt[NROWS];
__device__ int   g_topi[NTOK];
__device__ float g_w0[NTOK];
__device__ float g_w1[NTOK];
__device__ int   g_slot0[NTOK];
__device__ int   g_slot1[NTOK];
__device__ __half g_xf[(size_t)NTOK * DIM];            // fp16 x
__device__ __half g_wf[(size_t)NEXP * DIM * DIM];      // fp16 W
__device__ __half g_scr[(size_t)NROWS * DIM];          // fp16 slot scratch (128 MB)

// ---------------- PTX helpers (base-target PTX only) ----------------
__device__ __forceinline__ uint32_t smem_u32(const void* p) {
    uint32_t a;
    asm("{ .reg .u64 t; cvta.to.shared.u64 t, %1; cvt.u32.u64 %0, t; }" : "=r"(a) : "l"(p));
    return a;
}
__device__ __forceinline__ void cp16(uint32_t dst, const void* src) {
    asm volatile("cp.async.cg.shared.global [%0], [%1], 16;" :: "r"(dst), "l"(src));
}
#define CP_COMMIT() asm volatile("cp.async.commit_group;" ::: "memory")

#define LDSM4(r, addr) \
    asm volatile("ldmatrix.sync.aligned.m8n8.x4.shared.b16 {%0,%1,%2,%3}, [%4];" \
        : "=r"((r)[0]), "=r"((r)[1]), "=r"((r)[2]), "=r"((r)[3]) : "r"(addr))

#define MMA16816(d, a, b0, b1) \
    asm volatile("mma.sync.aligned.m16n8k16.row.col.f32.f16.f16.f32 " \
        "{%0,%1,%2,%3},{%4,%5,%6,%7},{%8,%9},{%0,%1,%2,%3};" \
        : "+f"((d)[0]), "+f"((d)[1]), "+f"((d)[2]), "+f"((d)[3]) \
        : "r"((a)[0]), "r"((a)[1]), "r"((a)[2]), "r"((a)[3]), "r"(b0), "r"(b1))

// ---------------- 1) convert W fp32 -> fp16 (+ zero counters, folded) -----
__global__ void conv_w_kernel(const float* __restrict__ W) {
    if (blockIdx.x == 0 && threadIdx.x < NEXP) {
        g_cnt[threadIdx.x] = 0;
        g_cur2[threadIdx.x] = 0;
        if (threadIdx.x == 0) g_tick = 0;
    }
    int i = blockIdx.x * 256 + threadIdx.x;
    float4 v = reinterpret_cast<const float4*>(W)[i];
    __half2 a = {__float2half(v.x), __float2half(v.y)};
    __half2 b = {__float2half(v.z), __float2half(v.w)};
    reinterpret_cast<__half2*>(g_wf)[i * 2 + 0] = a;
    reinterpret_cast<__half2*>(g_wf)[i * 2 + 1] = b;
}

// ---------------- 2) gating: 2 tokens/warp (Wg smem traffic halved) -------
// Per-token accumulation sequence is bit-identical to the 1-token version.
__global__ void gating_kernel(const float* __restrict__ x,
                              const float* __restrict__ Wg,
                              const float* __restrict__ bg) {
    __shared__ float4 sWg4[NEXP * 256];     // 32 KB
    __shared__ float sbg[NEXP];
    int tid = threadIdx.x;
    for (int i = tid; i < NEXP * 256; i += 256)
        sWg4[i] = reinterpret_cast<const float4*>(Wg)[i];
    if (tid < NEXP) sbg[tid] = bg[tid];
    __syncthreads();

    int warp = tid >> 5, lane = tid & 31;
    int t0 = blockIdx.x * 16 + warp * 2;       // tokens t0, t0+1
    const float4* xa4 = reinterpret_cast<const float4*>(x) + (size_t)t0 * 256;
    const float4* xb4 = xa4 + 256;
    __half2* xoa = reinterpret_cast<__half2*>(g_xf) + (size_t)t0 * 512;
    __half2* xob = xoa + 512;

    float acca[NEXP], accb[NEXP];
#pragma unroll
    for (int e = 0; e < NEXP; e++) { acca[e] = 0.f; accb[e] = 0.f; }

#pragma unroll
    for (int it = 0; it < 8; it++) {
        int j4 = it * 32 + lane;
        float4 xva = xa4[j4];
        float4 xvb = xb4[j4];
        xoa[j4 * 2 + 0] = {__float2half(xva.x), __float2half(xva.y)};
        xoa[j4 * 2 + 1] = {__float2half(xva.z), __float2half(xva.w)};
        xob[j4 * 2 + 0] = {__float2half(xvb.x), __float2half(xvb.y)};
        xob[j4 * 2 + 1] = {__float2half(xvb.z), __float2half(xvb.w)};
#pragma unroll
        for (int e = 0; e < NEXP; e++) {
            float4 wv = sWg4[e * 256 + j4];
            acca[e] += xva.x * wv.x + xva.y * wv.y + xva.z * wv.z + xva.w * wv.w;
            accb[e] += xvb.x * wv.x + xvb.y * wv.y + xvb.z * wv.z + xvb.w * wv.w;
        }
    }
#pragma unroll
    for (int e = 0; e < NEXP; e++) {
#pragma unroll
        for (int o = 16; o; o >>= 1) {
            acca[e] += __shfl_xor_sync(0xffffffffu, acca[e], o);
            accb[e] += __shfl_xor_sync(0xffffffffu, accb[e], o);
        }
    }

    if (lane == 0) {
#pragma unroll
        for (int tk = 0; tk < 2; tk++) {
            int t = t0 + tk;
            float* accp = tk ? accb : acca;
            float s[NEXP], m = -1e30f;
#pragma unroll
            for (int e = 0; e < NEXP; e++) { s[e] = accp[e] + sbg[e]; m = fmaxf(m, s[e]); }
            float p[NEXP], sum = 0.f;
#pragma unroll
            for (int e = 0; e < NEXP; e++) { p[e] = __expf(s[e] - m); sum += p[e]; }
            float inv = 1.f / sum;
#pragma unroll
            for (int e = 0; e < NEXP; e++) p[e] *= inv;
            int i0 = 0;
#pragma unroll
            for (int e = 1; e < NEXP; e++) if (p[e] > p[i0]) i0 = e;
            int i1 = -1;
#pragma unroll
            for (int e = 0; e < NEXP; e++) {
                if (e == i0) continue;
                if (i1 < 0 || p[e] > p[i1]) i1 = e;
            }
            g_topi[t] = i0 | (i1 << 8);
            g_w0[t] = p[i0];
            g_w1[t] = p[i1];
            atomicAdd(&g_cnt[i0], 1);
            atomicAdd(&g_cnt[i1], 1);
        }
    }
}

// ---------------- 3) scatter (local prefix scan; publishes offsets) -------
__global__ void scatter_kernel() {
    __shared__ int soff[NEXP];
    if (threadIdx.x == 0) {
        int o = 0;
#pragma unroll
        for (int e = 0; e < NEXP; e++) { soff[e] = o; o += g_cnt[e]; }
        if (blockIdx.x == 0) {          // publish for the GEMM kernel
            int o2 = 0, rt = 0;
#pragma unroll
            for (int e = 0; e < NEXP; e++) {
                g_off[e] = o2;
                g_toff[e] = rt;
                o2 += g_cnt[e];
                rt += (g_cnt[e] + 127) >> 7;
            }
            g_off[NEXP] = o2;
            g_toff[NEXP] = rt;
        }
    }
    __syncthreads();
    int t = blockIdx.x * blockDim.x + threadIdx.x;
    int pk = g_topi[t];
    int i0 = pk & 0xff, i1 = (pk >> 8) & 0xff;
    int p0 = soff[i0] + atomicAdd(&g_cur2[i0], 1);
    g_tok[p0] = t; g_wt[p0] = g_w0[t]; g_slot0[t] = p0;
    int p1 = soff[i1] + atomicAdd(&g_cur2[i1], 1);
    g_tok[p1] = t; g_wt[p1] = g_w1[t]; g_slot1[t] = p1;
}

// ---------------- 4) persistent grouped GEMM (ticket scheduler) -----------
#define KCHUNK 64
#define NSTG 3
#define ROWB 144
#define STG_A 0
#define STG_B 18432
#define STG_SZ 36864
#define HDR 2048
#define SMEM_TOTAL (HDR + NSTG * STG_SZ)   // 112640 (x2 CTA = 225280 <= 228KB)
#define NPERS 296                          // 148 SMs x 2 CTAs

extern __shared__ __align__(1024) char dyn_smem[];

struct GArgs {
    uint32_t sbase;
    const int* stok;
    int wbase;     // e*DIM + col0
    int tid;
};

__device__ __forceinline__ void load_A_half(const GArgs& a, int stage, int k0, int half) {
    uint32_t st = a.sbase + HDR + stage * STG_SZ;
#pragma unroll
    for (int q = 0; q < 2; q++) {
        int idx = (half * 2 + q) * 256 + a.tid;
        int row = idx >> 3, c = idx & 7;
        size_t src = (size_t)a.stok[row] * DIM + k0 + c * 8;
        cp16(st + STG_A + row * ROWB + c * 16, g_xf + src);
    }
}
__device__ __forceinline__ void load_B_half(const GArgs& a, int stage, int k0, int half) {
    uint32_t st = a.sbase + HDR + stage * STG_SZ;
#pragma unroll
    for (int q = 0; q < 2; q++) {
        int idx = (half * 2 + q) * 256 + a.tid;
        int row = idx >> 3, c = idx & 7;
        size_t src = (size_t)(a.wbase + row) * DIM + k0 + c * 8;
        cp16(st + STG_B + row * ROWB + c * 16, g_wf + src);
    }
}

__device__ __forceinline__ void compute_kstep(uint32_t st, int m0, int n0, int lane,
                                              int ks, float acc[2][8][4]) {
    uint32_t a[2][4];
#pragma unroll
    for (int fi = 0; fi < 2; fi++) {
        uint32_t addr = st + STG_A + (uint32_t)(m0 + fi * 16 + (lane & 15)) * ROWB
                      + ks * 32 + ((lane >> 4) << 4);
        LDSM4(a[fi], addr);
    }
#pragma unroll
    for (int fj2 = 0; fj2 < 4; fj2++) {
        uint32_t b[4];
        uint32_t addr = st + STG_B
            + (uint32_t)(n0 + fj2 * 16 + (((lane >> 4) & 1) << 3) + (lane & 7)) * ROWB
            + ks * 32 + (((lane >> 3) & 1) << 4);
        LDSM4(b, addr);
        MMA16816(acc[0][2 * fj2 + 0], a[0], b[0], b[1]);
        MMA16816(acc[0][2 * fj2 + 1], a[0], b[2], b[3]);
        MMA16816(acc[1][2 * fj2 + 0], a[1], b[0], b[1]);
        MMA16816(acc[1][2 * fj2 + 1], a[1], b[2], b[3]);
    }
}

__global__ __launch_bounds__(256, 2)
void moe_gemm_mma(const float* __restrict__ bias) {
    int* stok = reinterpret_cast<int*>(dyn_smem);
    float* swt = reinterpret_cast<float*>(dyn_smem + 512);
    float* sbias = reinterpret_cast<float*>(dyn_smem + 1024);
    int* s_tile = reinterpret_cast<int*>(dyn_smem + 1536);

    int tid = threadIdx.x;
    int lane = tid & 31, wid = tid >> 5;
    int m0 = (wid & 3) * 32, n0 = (wid >> 2) * 64;
    uint32_t sbase = smem_u32(dyn_smem);
    int total_tiles = g_toff[NEXP] * 8;

    while (true) {
        if (tid == 0) *s_tile = atomicAdd(&g_tick, 1);
        __syncthreads();                 // s_tile visible; prior epilogue done
        int t = *s_tile;
        if (t >= total_tiles) break;

        int rt = t >> 3;
        int col0 = (t & 7) * 128;
        int e = 0;
#pragma unroll
        for (int k = 0; k < NEXP - 1; k++) if (rt >= g_toff[k + 1]) e = k + 1;
        int base = g_off[e];
        int cnt = g_off[e + 1] - base;
        int row0 = (rt - g_toff[e]) * 128;

        if (tid < 128) {
            int p = row0 + tid;
            int pc = p < cnt ? p : cnt - 1;
            stok[tid] = g_tok[base + pc];
            swt[tid] = (p < cnt) ? g_wt[base + p] : 0.f;
        }
        if (tid < 32)
            reinterpret_cast<float4*>(sbias)[tid] =
                reinterpret_cast<const float4*>(bias + e * DIM + col0)[tid];
        __syncthreads();                 // header visible

        GArgs ga{sbase, stok, e * DIM + col0, tid};

        load_A_half(ga, 0, 0, 0);      load_A_half(ga, 0, 0, 1);
        load_B_half(ga, 0, 0, 0);      load_B_half(ga, 0, 0, 1);      CP_COMMIT();
        load_A_half(ga, 1, KCHUNK, 0); load_A_half(ga, 1, KCHUNK, 1);
        load_B_half(ga, 1, KCHUNK, 0); load_B_half(ga, 1, KCHUNK, 1); CP_COMMIT();

        float acc[2][8][4];
#pragma unroll
        for (int i = 0; i < 2; i++)
#pragma unroll
            for (int j = 0; j < 8; j++)
#pragma unroll
                for (int k = 0; k < 4; k++) acc[i][j][k] = 0.f;

        const int NIT = DIM / KCHUNK;   // 16
#pragma unroll
        for (int i = 0; i < NIT; i++) {
            int s = i % 3;
            asm volatile("cp.async.wait_group 1;" ::: "memory");
            __syncthreads();
            uint32_t stg = sbase + HDR + s * STG_SZ;
            int nstage = (i + 2) % 3;
            bool doload = (i + 2) < NIT;
            int nk0 = (i + 2) * KCHUNK;
            compute_kstep(stg, m0, n0, lane, 0, acc);
            if (doload) load_A_half(ga, nstage, nk0, 0);
            compute_kstep(stg, m0, n0, lane, 1, acc);
            if (doload) load_A_half(ga, nstage, nk0, 1);
            compute_kstep(stg, m0, n0, lane, 2, acc);
            if (doload) load_B_half(ga, nstage, nk0, 0);
            compute_kstep(stg, m0, n0, lane, 3, acc);
            if (doload) load_B_half(ga, nstage, nk0, 1);
            CP_COMMIT();                // exactly one group per iteration
        }

        // epilogue: scaled (+bias) fp16 write to slot scratch
        int tq = lane >> 2, tr = lane & 3;
#pragma unroll
        for (int fi = 0; fi < 2; fi++) {
#pragma unroll
            for (int h = 0; h < 2; h++) {
                int m = m0 + fi * 16 + h * 8 + tq;
                int gr = row0 + m;
                if (gr < cnt) {
                    float w = swt[m];
                    __half* orow = g_scr + (size_t)(base + gr) * DIM + col0;
#pragma unroll
                    for (int fj = 0; fj < 8; fj++) {
                        int cn = n0 + fj * 8 + tr * 2;
                        float vx = w * (acc[fi][fj][h * 2 + 0] + sbias[cn]);
                        float vy = w * (acc[fi][fj][h * 2 + 1] + sbias[cn + 1]);
                        *reinterpret_cast<__half2*>(orow + cn) = __floats2half2_rn(vx, vy);
                    }
                }
            }
        }
    }
}

// ---------------- 5) combine (fp16 scr -> fp32 out) ----------------
__global__ void combine_kernel(float* __restrict__ out) {
    int idx = blockIdx.x * 256 + threadIdx.x;   // 8-half chunk index
    int t = idx >> 7;                            // 128 chunks per token
    int c = idx & 127;
    const uint4* s4 = reinterpret_cast<const uint4*>(g_scr);
    uint4 a = s4[(size_t)g_slot0[t] * 128 + c];
    uint4 b = s4[(size_t)g_slot1[t] * 128 + c];
    const __half2* ah = reinterpret_cast<const __half2*>(&a);
    const __half2* bh = reinterpret_cast<const __half2*>(&b);
    float4 o0, o1;
    float2 p0 = __half22float2(ah[0]), q0 = __half22float2(bh[0]);
    float2 p1 = __half22float2(ah[1]), q1 = __half22float2(bh[1]);
    float2 p2 = __half22float2(ah[2]), q2 = __half22float2(bh[2]);
    float2 p3 = __half22float2(ah[3]), q3 = __half22float2(bh[3]);
    o0.x = p0.x + q0.x; o0.y = p0.y + q0.y; o0.z = p1.x + q1.x; o0.w = p1.y + q1.y;
    o1.x = p2.x + q2.x; o1.y = p2.y + q2.y; o1.z = p3.x + q3.x; o1.w = p3.y + q3.y;
    float4* out4 = reinterpret_cast<float4*>(out);
    out4[idx * 2 + 0] = o0;
    out4[idx * 2 + 1] = o1;
}

// ---------------------------------------------------------------------------
extern "C" void kernel_launch(void* const* d_in, const int* in_sizes, int n_in,
                              void* d_out, int out_size) {
    const float* x  = (const float*)d_in[0];
    const float* Wg = (const float*)d_in[1];
    const float* bg = (const float*)d_in[2];
    const float* W  = (const float*)d_in[3];
    const float* b  = (const float*)d_in[4];
    float* out = (float*)d_out;

    cudaFuncSetAttribute(moe_gemm_mma, cudaFuncAttributeMaxDynamicSharedMemorySize,
                         SMEM_TOTAL);

    conv_w_kernel<<<(NEXP * DIM * DIM) / (4 * 256), 256>>>(W);
    gating_kernel<<<NTOK / 16, 256>>>(x, Wg, bg);
    scatter_kernel<<<NTOK / 256, 256>>>();
    moe_gemm_mma<<<NPERS, 256, SMEM_TOTAL>>>(b);
    combine_kernel<<<(NTOK * DIM) / (8 * 256), 256>>>(out);
}

// round 17
// speedup vs baseline: 1.1824x; 1.0170x over previous
#include <cuda_runtime.h>
#include <cuda_fp16.h>
#include <cstdint>

#define NTOK 32768
#define DIM 1024
#define NEXP 8
#define NROWS (NTOK * 2)

// ---------------- device scratch (no allocation allowed) ----------------
__device__ int   g_cnt[NEXP];
__device__ int   g_off[NEXP + 1];
__device__ int   g_cur2[NEXP];
__device__ int   g_tok[NROWS];
__device__ float g_wt[NROWS];
__device__ int   g_topi[NTOK];
__device__ float g_w0[NTOK];
__device__ float g_w1[NTOK];
__device__ int   g_slot0[NTOK];
__device__ int   g_slot1[NTOK];
__device__ __half g_xf[(size_t)NTOK * DIM];            // fp16 x
__device__ __half g_wf[(size_t)NEXP * DIM * DIM];      // fp16 W
__device__ __half g_scr[(size_t)NROWS * DIM];          // fp16 slot scratch (128 MB)

// ---------------- PTX helpers (base-target PTX only) ----------------
__device__ __forceinline__ uint32_t smem_u32(const void* p) {
    uint32_t a;
    asm("{ .reg .u64 t; cvta.to.shared.u64 t, %1; cvt.u32.u64 %0, t; }" : "=r"(a) : "l"(p));
    return a;
}
__device__ __forceinline__ void cp16(uint32_t dst, const void* src) {
    asm volatile("cp.async.cg.shared.global [%0], [%1], 16;" :: "r"(dst), "l"(src));
}
#define CP_COMMIT() asm volatile("cp.async.commit_group;" ::: "memory")

#define LDSM4(r, addr) \
    asm volatile("ldmatrix.sync.aligned.m8n8.x4.shared.b16 {%0,%1,%2,%3}, [%4];" \
        : "=r"((r)[0]), "=r"((r)[1]), "=r"((r)[2]), "=r"((r)[3]) : "r"(addr))

#define MMA16816(d, a, b0, b1) \
    asm volatile("mma.sync.aligned.m16n8k16.row.col.f32.f16.f16.f32 " \
        "{%0,%1,%2,%3},{%4,%5,%6,%7},{%8,%9},{%0,%1,%2,%3};" \
        : "+f"((d)[0]), "+f"((d)[1]), "+f"((d)[2]), "+f"((d)[3]) \
        : "r"((a)[0]), "r"((a)[1]), "r"((a)[2]), "r"((a)[3]), "r"(b0), "r"(b1))

// ---------------- 1) convert W fp32 -> fp16 (+ zero counters, folded) -----
__global__ void conv_w_kernel(const float* __restrict__ W) {
    if (blockIdx.x == 0 && threadIdx.x < NEXP) {
        g_cnt[threadIdx.x] = 0;
        g_cur2[threadIdx.x] = 0;
    }
    int i = blockIdx.x * 256 + threadIdx.x;
    float4 v = reinterpret_cast<const float4*>(W)[i];
    __half2 a = {__float2half(v.x), __float2half(v.y)};
    __half2 b = {__float2half(v.z), __float2half(v.w)};
    reinterpret_cast<__half2*>(g_wf)[i * 2 + 0] = a;
    reinterpret_cast<__half2*>(g_wf)[i * 2 + 1] = b;
}

// ---------------- 2) gating: 2 tokens/warp (Wg smem traffic halved) -------
// Per-token accumulation sequence is bit-identical to the 1-token version.
__global__ void gating_kernel(const float* __restrict__ x,
                              const float* __restrict__ Wg,
                              const float* __restrict__ bg) {
    __shared__ float4 sWg4[NEXP * 256];     // 32 KB
    __shared__ float sbg[NEXP];
    int tid = threadIdx.x;
    for (int i = tid; i < NEXP * 256; i += 256)
        sWg4[i] = reinterpret_cast<const float4*>(Wg)[i];
    if (tid < NEXP) sbg[tid] = bg[tid];
    __syncthreads();

    int warp = tid >> 5, lane = tid & 31;
    int t0 = blockIdx.x * 16 + warp * 2;       // tokens t0, t0+1
    const float4* xa4 = reinterpret_cast<const float4*>(x) + (size_t)t0 * 256;
    const float4* xb4 = xa4 + 256;
    __half2* xoa = reinterpret_cast<__half2*>(g_xf) + (size_t)t0 * 512;
    __half2* xob = xoa + 512;

    float acca[NEXP], accb[NEXP];
#pragma unroll
    for (int e = 0; e < NEXP; e++) { acca[e] = 0.f; accb[e] = 0.f; }

#pragma unroll
    for (int it = 0; it < 8; it++) {
        int j4 = it * 32 + lane;
        float4 xva = xa4[j4];
        float4 xvb = xb4[j4];
        xoa[j4 * 2 + 0] = {__float2half(xva.x), __float2half(xva.y)};
        xoa[j4 * 2 + 1] = {__float2half(xva.z), __float2half(xva.w)};
        xob[j4 * 2 + 0] = {__float2half(xvb.x), __float2half(xvb.y)};
        xob[j4 * 2 + 1] = {__float2half(xvb.z), __float2half(xvb.w)};
#pragma unroll
        for (int e = 0; e < NEXP; e++) {
            float4 wv = sWg4[e * 256 + j4];
            acca[e] += xva.x * wv.x + xva.y * wv.y + xva.z * wv.z + xva.w * wv.w;
            accb[e] += xvb.x * wv.x + xvb.y * wv.y + xvb.z * wv.z + xvb.w * wv.w;
        }
    }
#pragma unroll
    for (int e = 0; e < NEXP; e++) {
#pragma unroll
        for (int o = 16; o; o >>= 1) {
            acca[e] += __shfl_xor_sync(0xffffffffu, acca[e], o);
            accb[e] += __shfl_xor_sync(0xffffffffu, accb[e], o);
        }
    }

    if (lane == 0) {
#pragma unroll
        for (int tk = 0; tk < 2; tk++) {
            int t = t0 + tk;
            float* accp = tk ? accb : acca;
            float s[NEXP], m = -1e30f;
#pragma unroll
            for (int e = 0; e < NEXP; e++) { s[e] = accp[e] + sbg[e]; m = fmaxf(m, s[e]); }
            float p[NEXP], sum = 0.f;
#pragma unroll
            for (int e = 0; e < NEXP; e++) { p[e] = __expf(s[e] - m); sum += p[e]; }
            float inv = 1.f / sum;
#pragma unroll
            for (int e = 0; e < NEXP; e++) p[e] *= inv;
            int i0 = 0;
#pragma unroll
            for (int e = 1; e < NEXP; e++) if (p[e] > p[i0]) i0 = e;
            int i1 = -1;
#pragma unroll
            for (int e = 0; e < NEXP; e++) {
                if (e == i0) continue;
                if (i1 < 0 || p[e] > p[i1]) i1 = e;
            }
            g_topi[t] = i0 | (i1 << 8);
            g_w0[t] = p[i0];
            g_w1[t] = p[i1];
            atomicAdd(&g_cnt[i0], 1);
            atomicAdd(&g_cnt[i1], 1);
        }
    }
}

// ---------------- 3) scatter (local prefix scan; publishes offsets) -------
__global__ void scatter_kernel() {
    __shared__ int soff[NEXP];
    if (threadIdx.x == 0) {
        int o = 0;
#pragma unroll
        for (int e = 0; e < NEXP; e++) { soff[e] = o; o += g_cnt[e]; }
        if (blockIdx.x == 0) {          // publish for the GEMM kernel
            int o2 = 0;
#pragma unroll
            for (int e = 0; e < NEXP; e++) { g_off[e] = o2; o2 += g_cnt[e]; }
            g_off[NEXP] = o2;
        }
    }
    __syncthreads();
    int t = blockIdx.x * blockDim.x + threadIdx.x;
    int pk = g_topi[t];
    int i0 = pk & 0xff, i1 = (pk >> 8) & 0xff;
    int p0 = soff[i0] + atomicAdd(&g_cur2[i0], 1);
    g_tok[p0] = t; g_wt[p0] = g_w0[t]; g_slot0[t] = p0;
    int p1 = soff[i1] + atomicAdd(&g_cur2[i1], 1);
    g_tok[p1] = t; g_wt[p1] = g_w1[t]; g_slot1[t] = p1;
}

// ---------------- 4) grouped GEMM: KCHUNK=64, 3 stages, unrolled mainloop -
#define KCHUNK 64
#define NSTG 3
#define ROWB 144
#define STG_A 0
#define STG_B 18432
#define STG_SZ 36864
#define HDR 2048
#define SMEM_TOTAL (HDR + NSTG * STG_SZ)   // 112640 (x2 CTA = 225280 <= 228KB)

extern __shared__ __align__(1024) char dyn_smem[];

struct GArgs {
    uint32_t sbase;
    const int* stok;
    int wbase;     // e*DIM + col0
    int tid;
};

// half in {0,1}: two 16B-chunk quarters of the A plane (2 cp.async/thread)
__device__ __forceinline__ void load_A_half(const GArgs& a, int stage, int k0, int half) {
    uint32_t st = a.sbase + HDR + stage * STG_SZ;
#pragma unroll
    for (int q = 0; q < 2; q++) {
        int idx = (half * 2 + q) * 256 + a.tid;
        int row = idx >> 3, c = idx & 7;
        size_t src = (size_t)a.stok[row] * DIM + k0 + c * 8;
        cp16(st + STG_A + row * ROWB + c * 16, g_xf + src);
    }
}
__device__ __forceinline__ void load_B_half(const GArgs& a, int stage, int k0, int half) {
    uint32_t st = a.sbase + HDR + stage * STG_SZ;
#pragma unroll
    for (int q = 0; q < 2; q++) {
        int idx = (half * 2 + q) * 256 + a.tid;
        int row = idx >> 3, c = idx & 7;
        size_t src = (size_t)(a.wbase + row) * DIM + k0 + c * 8;
        cp16(st + STG_B + row * ROWB + c * 16, g_wf + src);
    }
}

// One K=16 step: 6 LDSM + 16 MMA. ks in 0..3 selects 32B column offset.
__device__ __forceinline__ void compute_kstep(uint32_t st, int m0, int n0, int lane,
                                              int ks, float acc[2][8][4]) {
    uint32_t a[2][4];
#pragma unroll
    for (int fi = 0; fi < 2; fi++) {
        uint32_t addr = st + STG_A + (uint32_t)(m0 + fi * 16 + (lane & 15)) * ROWB
                      + ks * 32 + ((lane >> 4) << 4);
        LDSM4(a[fi], addr);
    }
#pragma unroll
    for (int fj2 = 0; fj2 < 4; fj2++) {
        uint32_t b[4];
        uint32_t addr = st + STG_B
            + (uint32_t)(n0 + fj2 * 16 + (((lane >> 4) & 1) << 3) + (lane & 7)) * ROWB
            + ks * 32 + (((lane >> 3) & 1) << 4);
        LDSM4(b, addr);
        MMA16816(acc[0][2 * fj2 + 0], a[0], b[0], b[1]);
        MMA16816(acc[0][2 * fj2 + 1], a[0], b[2], b[3]);
        MMA16816(acc[1][2 * fj2 + 0], a[1], b[0], b[1]);
        MMA16816(acc[1][2 * fj2 + 1], a[1], b[2], b[3]);
    }
}

__global__ __launch_bounds__(256, 2)
void moe_gemm_mma(const float* __restrict__ bias) {
    int e = blockIdx.z;
    int base = g_off[e];
    int cnt = g_off[e + 1] - base;
    int row0 = blockIdx.y * 128;
    if (row0 >= cnt) return;
    int col0 = blockIdx.x * 128;

    int* stok = reinterpret_cast<int*>(dyn_smem);
    float* swt = reinterpret_cast<float*>(dyn_smem + 512);
    float* sbias = reinterpret_cast<float*>(dyn_smem + 1024);

    int tid = threadIdx.x;
    if (tid < 128) {
        int p = row0 + tid;
        int pc = p < cnt ? p : cnt - 1;
        stok[tid] = g_tok[base + pc];
        swt[tid] = (p < cnt) ? g_wt[base + p] : 0.f;
    }
    if (tid < 32)
        reinterpret_cast<float4*>(sbias)[tid] =
            reinterpret_cast<const float4*>(bias + e * DIM + col0)[tid];
    __syncthreads();

    uint32_t sbase = smem_u32(dyn_smem);
    GArgs ga{sbase, stok, e * DIM + col0, tid};

    // prologue: stages 0 and 1 (one commit group each)
    load_A_half(ga, 0, 0, 0);      load_A_half(ga, 0, 0, 1);
    load_B_half(ga, 0, 0, 0);      load_B_half(ga, 0, 0, 1);      CP_COMMIT();
    load_A_half(ga, 1, KCHUNK, 0); load_A_half(ga, 1, KCHUNK, 1);
    load_B_half(ga, 1, KCHUNK, 0); load_B_half(ga, 1, KCHUNK, 1); CP_COMMIT();

    int lane = tid & 31, wid = tid >> 5;
    int m0 = (wid & 3) * 32, n0 = (wid >> 2) * 64;

    float acc[2][8][4];
#pragma unroll
    for (int i = 0; i < 2; i++)
#pragma unroll
        for (int j = 0; j < 8; j++)
#pragma unroll
            for (int k = 0; k < 4; k++) acc[i][j][k] = 0.f;

    const int NIT = DIM / KCHUNK;   // 16
#pragma unroll
    for (int i = 0; i < NIT; i++) {
        int s = i % 3;               // constant after full unroll
        // committed groups before this wait: 2 + i; wait_group 1 -> groups
        // 0..i complete, so stage s (= group i) is resident.
        asm volatile("cp.async.wait_group 1;" ::: "memory");
        __syncthreads();
        uint32_t stg = sbase + HDR + s * STG_SZ;
        int nstage = (i + 2) % 3;       // == (i-1)%3: all warps done reading it
        bool doload = (i + 2) < NIT;
        int nk0 = (i + 2) * KCHUNK;
        // 4-way interleave: tiny LSU bursts in the shadow of each kstep's MMAs
        compute_kstep(stg, m0, n0, lane, 0, acc);
        if (doload) load_A_half(ga, nstage, nk0, 0);
        compute_kstep(stg, m0, n0, lane, 1, acc);
        if (doload) load_A_half(ga, nstage, nk0, 1);
        compute_kstep(stg, m0, n0, lane, 2, acc);
        if (doload) load_B_half(ga, nstage, nk0, 0);
        compute_kstep(stg, m0, n0, lane, 3, acc);
        if (doload) load_B_half(ga, nstage, nk0, 1);
        CP_COMMIT();                    // exactly one group per iteration
    }

    // epilogue: scaled (+bias) fp16 write to slot scratch
    int tq = lane >> 2, tr = lane & 3;
#pragma unroll
    for (int fi = 0; fi < 2; fi++) {
#pragma unroll
        for (int h = 0; h < 2; h++) {
            int m = m0 + fi * 16 + h * 8 + tq;
            int gr = row0 + m;
            if (gr < cnt) {
                float w = swt[m];
                __half* orow = g_scr + (size_t)(base + gr) * DIM + col0;
#pragma unroll
                for (int fj = 0; fj < 8; fj++) {
                    int cn = n0 + fj * 8 + tr * 2;
                    float vx = w * (acc[fi][fj][h * 2 + 0] + sbias[cn]);
                    float vy = w * (acc[fi][fj][h * 2 + 1] + sbias[cn + 1]);
                    *reinterpret_cast<__half2*>(orow + cn) = __floats2half2_rn(vx, vy);
                }
            }
        }
    }
}

// ---------------- 5) combine (fp16 scr -> fp32 out) ----------------
__global__ void combine_kernel(float* __restrict__ out) {
    int idx = blockIdx.x * 256 + threadIdx.x;   // 8-half chunk index
    int t = idx >> 7;                            // 128 chunks per token
    int c = idx & 127;
    const uint4* s4 = reinterpret_cast<const uint4*>(g_scr);
    uint4 a = s4[(size_t)g_slot0[t] * 128 + c];
    uint4 b = s4[(size_t)g_slot1[t] * 128 + c];
    const __half2* ah = reinterpret_cast<const __half2*>(&a);
    const __half2* bh = reinterpret_cast<const __half2*>(&b);
    float4 o0, o1;
    float2 p0 = __half22float2(ah[0]), q0 = __half22float2(bh[0]);
    float2 p1 = __half22float2(ah[1]), q1 = __half22float2(bh[1]);
    float2 p2 = __half22float2(ah[2]), q2 = __half22float2(bh[2]);
    float2 p3 = __half22float2(ah[3]), q3 = __half22float2(bh[3]);
    o0.x = p0.x + q0.x; o0.y = p0.y + q0.y; o0.z = p1.x + q1.x; o0.w = p1.y + q1.y;
    o1.x = p2.x + q2.x; o1.y = p2.y + q2.y; o1.z = p3.x + q3.x; o1.w = p3.y + q3.y;
    float4* out4 = reinterpret_cast<float4*>(out);
    out4[idx * 2 + 0] = o0;
    out4[idx * 2 + 1] = o1;
}

// ---------------------------------------------------------------------------
extern "C" void kernel_launch(void* const* d_in, const int* in_sizes, int n_in,
                              void* d_out, int out_size) {
    const float* x  = (const float*)d_in[0];
    const float* Wg = (const float*)d_in[1];
    const float* bg = (const float*)d_in[2];
    const float* W  = (const float*)d_in[3];
    const float* b  = (const float*)d_in[4];
    float* out = (float*)d_out;

    cudaFuncSetAttribute(moe_gemm_mma, cudaFuncAttributeMaxDynamicSharedMemorySize,
                         SMEM_TOTAL);

    conv_w_kernel<<<(NEXP * DIM * DIM) / (4 * 256), 256>>>(W);
    gating_kernel<<<NTOK / 16, 256>>>(x, Wg, bg);
    scatter_kernel<<<NTOK / 256, 256>>>();
    moe_gemm_mma<<<dim3(8, 512, 8), 256, SMEM_TOTAL>>>(b);
    combine_kernel<<<(NTOK * DIM) / (8 * 256), 256>>>(out);
}